// round 12
// baseline (speedup 1.0000x reference)
#include <cuda_runtime.h>
#include <cuda_fp16.h>
#include <cstdint>

#define C_N 512
#define D_N 256
#define H_N 512
#define M_N 256
#define OH_N 512
#define E_N 261632

// ---------------------------------------------------------------------------
// Device scratch
// ---------------------------------------------------------------------------
__device__ __align__(16) __half g_Ph[4 * C_N * H_N];    // layer-1 projections, fp16
__device__ __align__(16) __half g_W2TH[2 * M_N * H_N];  // W2 transposed [t][n][k], fp16
__device__ __align__(16) float  g_agg[C_N * M_N];
__device__ __align__(16) float  g_h1[C_N * OH_N];
__device__ __align__(16) float  g_h2[C_N * OH_N];
__device__ int g_hist[512];
__device__ int g_cursor[512];
__device__ int g_perm[E_N];

// ---------------------------------------------------------------------------
// Helpers
// ---------------------------------------------------------------------------
__device__ __forceinline__ uint32_t smem_u32(const void* p) {
    uint32_t a;
    asm("{ .reg .u64 t; cvta.to.shared.u64 t, %1; cvt.u32.u64 %0, t; }" : "=r"(a) : "l"(p));
    return a;
}
__device__ __forceinline__ void cp16(uint32_t dst, const void* src) {
    asm volatile("cp.async.cg.shared.global [%0], [%1], 16;" :: "r"(dst), "l"(src));
}
#define CP_COMMIT() asm volatile("cp.async.commit_group;" ::: "memory")
#define CP_WAIT0()  asm volatile("cp.async.wait_group 0;" ::: "memory")

__device__ __forceinline__ void mma_f16(float* c, const uint32_t* a, const uint32_t* b) {
    asm volatile(
        "mma.sync.aligned.m16n8k16.row.col.f32.f16.f16.f32 "
        "{%0,%1,%2,%3}, {%4,%5,%6,%7}, {%8,%9}, {%0,%1,%2,%3};"
        : "+f"(c[0]), "+f"(c[1]), "+f"(c[2]), "+f"(c[3])
        : "r"(a[0]), "r"(a[1]), "r"(a[2]), "r"(a[3]), "r"(b[0]), "r"(b[1]));
}
__device__ __forceinline__ void ldmx4(uint32_t* r, uint32_t addr) {
    asm volatile("ldmatrix.sync.aligned.m8n8.x4.shared.b16 {%0,%1,%2,%3}, [%4];"
                 : "=r"(r[0]), "=r"(r[1]), "=r"(r[2]), "=r"(r[3]) : "r"(addr));
}

// ---------------------------------------------------------------------------
// fp32 GEMM body (64x64 tile, 256 thr) — proven R2..R11
// ---------------------------------------------------------------------------
__device__ __forceinline__ void gemm64_body(const float* __restrict__ A,
                                            const float* __restrict__ B,
                                            const float* __restrict__ bias,
                                            float* __restrict__ Cf,
                                            __half* __restrict__ Ch,
                                            int K, int N, int doRelu, int m0, int n0)
{
    __shared__ __align__(16) float sA[64][20];
    __shared__ __align__(16) float sB[16][64];

    int tid = threadIdx.x;
    int tx = tid & 15, ty = tid >> 4;
    float acc[4][4] = {};

    for (int k0 = 0; k0 < K; k0 += 16) {
        {
            int row = tid >> 2, cs = (tid & 3) * 4;
            float4 v = *(const float4*)(A + (m0 + row) * K + k0 + cs);
            *(float4*)&sA[row][cs] = v;
        }
        {
            int kk = tid >> 4, cs = (tid & 15) * 4;
            float4 v = *(const float4*)(B + (k0 + kk) * N + n0 + cs);
            *(float4*)&sB[kk][cs] = v;
        }
        __syncthreads();
        #pragma unroll
        for (int k = 0; k < 16; k++) {
            float a[4];
            #pragma unroll
            for (int i = 0; i < 4; i++) a[i] = sA[ty * 4 + i][k];
            float4 bv = *(const float4*)&sB[k][tx * 4];
            #pragma unroll
            for (int i = 0; i < 4; i++) {
                acc[i][0] = fmaf(a[i], bv.x, acc[i][0]);
                acc[i][1] = fmaf(a[i], bv.y, acc[i][1]);
                acc[i][2] = fmaf(a[i], bv.z, acc[i][2]);
                acc[i][3] = fmaf(a[i], bv.w, acc[i][3]);
            }
        }
        __syncthreads();
    }

    #pragma unroll
    for (int i = 0; i < 4; i++) {
        #pragma unroll
        for (int j = 0; j < 4; j++) {
            int n = n0 + tx * 4 + j;
            float v = acc[i][j] + (bias ? bias[n] : 0.0f);
            if (doRelu) v = fmaxf(v, 0.0f);
            if (Cf) Cf[(m0 + ty * 4 + i) * N + n] = v;
            else    Ch[(m0 + ty * 4 + i) * N + n] = __float2half_rn(v);
        }
    }
}

__global__ __launch_bounds__(256, 4)
void gemm64(const float* __restrict__ A, const float* __restrict__ B,
            const float* __restrict__ bias, float* __restrict__ Cmat,
            int K, int N, int doRelu)
{
    gemm64_body(A, B, bias, Cmat, nullptr, K, N, doRelu, blockIdx.y * 64, blockIdx.x * 64);
}

__global__ __launch_bounds__(256, 4)
void layer1_gemm_h(const float* __restrict__ inputs, const float* __restrict__ W1,
                   const float* __restrict__ b1)
{
    int z = blockIdx.z;
    const float* B = W1 + (size_t)z * D_N * H_N;
    const float* bias = ((z & 1) == 0) ? (b1 + (size_t)(z >> 1) * H_N) : nullptr;
    __half* outp = g_Ph + (size_t)z * C_N * H_N;
    gemm64_body(inputs, B, bias, nullptr, outp, D_N, H_N, 0, blockIdx.y * 64, blockIdx.x * 64);
}

__global__ void transpose_w2_h(const float* __restrict__ W2)
{
    __shared__ float tile[32][33];
    int t = blockIdx.z, k0 = blockIdx.x * 32, n0 = blockIdx.y * 32;
    const float* src = W2 + (size_t)t * H_N * M_N;
    __half* dst = g_W2TH + (size_t)t * M_N * H_N;
    #pragma unroll
    for (int i = 0; i < 4; i++)
        tile[threadIdx.y + i * 8][threadIdx.x] =
            src[(size_t)(k0 + threadIdx.y + i * 8) * M_N + n0 + threadIdx.x];
    __syncthreads();
    #pragma unroll
    for (int i = 0; i < 4; i++)
        dst[(size_t)(n0 + threadIdx.y + i * 8) * H_N + k0 + threadIdx.x] =
            __float2half_rn(tile[threadIdx.x][threadIdx.y + i * 8]);
}

// ---------------------------------------------------------------------------
// Counting sort of edges by receiver (proven R7/R11)
// ---------------------------------------------------------------------------
__global__ void zero_kernel()
{
    int i = blockIdx.x * blockDim.x + threadIdx.x;
    if (i < C_N * M_N) g_agg[i] = 0.0f;
    if (i < 512) g_hist[i] = 0;
}

__global__ __launch_bounds__(512)
void hist_kernel(const int* __restrict__ rec)
{
    __shared__ int h[512];
    int tid = threadIdx.x;
    h[tid] = 0;
    __syncthreads();
    for (int e = blockIdx.x * 512 + tid; e < E_N; e += gridDim.x * 512)
        atomicAdd(&h[rec[e]], 1);
    __syncthreads();
    atomicAdd(&g_hist[tid], h[tid]);
}

__global__ __launch_bounds__(512)
void scan_kernel()
{
    __shared__ int tmp[2][512];
    int tid = threadIdx.x;
    int v = g_hist[tid];
    tmp[0][tid] = v;
    __syncthreads();
    int src = 0;
    for (int off = 1; off < 512; off <<= 1) {
        int val = tmp[src][tid];
        if (tid >= off) val += tmp[src][tid - off];
        tmp[src ^ 1][tid] = val;
        src ^= 1;
        __syncthreads();
    }
    g_cursor[tid] = tmp[src][tid] - v;   // exclusive prefix
}

__global__ __launch_bounds__(256)
void mkperm_kernel(const int* __restrict__ rec)
{
    for (int e = blockIdx.x * blockDim.x + threadIdx.x; e < E_N;
         e += gridDim.x * blockDim.x) {
        int c = rec[e];
        int pos = atomicAdd(&g_cursor[c], 1);
        g_perm[pos] = e;
    }
}

// ---------------------------------------------------------------------------
// Edge kernel v8: CTA = 256 SORTED edges x 128 cols x ONE type. 512 thr,
// 16 warps (4m x 4n), warp tile 64x32, ldmatrix fragments.
// B fully RESIDENT in smem (loaded once). A TRIPLE-buffered so the P-gather
// LDG is issued a full iteration before its store -> latency fully hidden.
// One __syncthreads per kc. R11 shfl-reduced scatter epilogue.
// ---------------------------------------------------------------------------
#define ET 256
#define ROWA 40
#define ROWB 520
#define A_STAGE_H (ET * ROWA)        // 10240 halves (20KB)
#define B_FULL_H  (128 * ROWB)       // 66560 halves (133KB)
#define NKC (H_N / 32)               // 16
#define EDGE_SMEM ((B_FULL_H + 3 * A_STAGE_H) * 2)   // 194560 B

__global__ __launch_bounds__(512, 1)
void edge_mma_kernel(const float* __restrict__ b2, const float* __restrict__ rel,
                     const int* __restrict__ send, const int* __restrict__ rec)
{
    extern __shared__ __align__(16) __half dsm[];
    __half* sBfull = dsm;                      // [128][ROWB]
    __half* sAbuf  = dsm + B_FULL_H;           // 3 stages [ET][ROWA]
    __shared__ float s_relt[ET];
    __shared__ int   s_r[ET];
    __shared__ int   s_p[ET];
    __shared__ float s_b2[128];

    const int tid  = threadIdx.x;
    const int lane = tid & 31;
    const int warp = tid >> 5;
    const int mb  = (warp & 3) * 64;      // 64-edge strip
    const int nbw = (warp >> 2) * 32;     // 32-col strip
    const int e0 = blockIdx.x * ET;
    const int n0 = blockIdx.y * 128;
    const int t  = blockIdx.z;
    const int r4 = lane >> 2, c4 = lane & 3;

    if (tid < ET) {
        int p = g_perm[e0 + tid];
        s_p[tid] = p;
        s_r[tid] = rec[p];
        s_relt[tid] = rel[(size_t)p * 2 + t];
    }
    if (tid < 128) s_b2[tid] = b2[t * M_N + n0 + tid];
    __syncthreads();

    // A staging: 2 threads per edge, 16 halves (2x16B) each
    const int le = tid >> 1;
    const int lq = tid & 1;
    const int sn = send[s_p[le]];
    const int rn = s_r[le];

    const uint32_t sB_u32 = smem_u32(sBfull);
    const uint32_t sA_u32 = smem_u32(sAbuf);

    const __half* PS = g_Ph + ((size_t)(t * 2 + 0) * C_N + sn) * H_N + lq * 16;
    const __half* PR = g_Ph + ((size_t)(t * 2 + 1) * C_N + rn) * H_N + lq * 16;

    // B resident load: 4 threads per row, 128 halves (256B) each
    {
        const int row = tid >> 2;
        const int bq = tid & 3;
        const __half* src = g_W2TH + ((size_t)t * M_N + n0 + row) * H_N + bq * 128;
        uint32_t d = sB_u32 + (uint32_t)(row * ROWB + bq * 128) * 2u;
        #pragma unroll
        for (int j = 0; j < 16; j++)
            cp16(d + j * 16, src + j * 8);
        CP_COMMIT();
    }

    // ldmatrix per-lane base addresses (bytes)
    const int lrA = lane & 15;
    const int khA = (lane >> 4) * 8;
    const int lrB = ((lane >> 4) & 1) * 8 + (lane & 7);
    const int khB = ((lane >> 3) & 1) * 8;
    uint32_t aBase[4], bBase[2];
    #pragma unroll
    for (int mt = 0; mt < 4; mt++)
        aBase[mt] = sA_u32 + (uint32_t)((mb + mt * 16 + lrA) * ROWA + khA) * 2u;
    #pragma unroll
    for (int p = 0; p < 2; p++)
        bBase[p] = sB_u32 + (uint32_t)((nbw + p * 16 + lrB) * ROWB + khB) * 2u;

    float acc[4][4][4];
    #pragma unroll
    for (int i = 0; i < 4; i++)
        #pragma unroll
        for (int j = 0; j < 4; j++)
            #pragma unroll
            for (int q = 0; q < 4; q++) acc[i][j][q] = 0.0f;

    const __half2 zero2 = __float2half2_rn(0.0f);
    uint4 pa0, pa1, pb0, pb1;

    // helper lambda replacements via macro for A compute+store
#define A_RELU_STORE(stOff)                                                   \
    do {                                                                      \
        __half2 hh[8];                                                        \
        const __half2* xa0 = (const __half2*)&pa0;                            \
        const __half2* xa1 = (const __half2*)&pa1;                            \
        const __half2* xb0 = (const __half2*)&pb0;                            \
        const __half2* xb1 = (const __half2*)&pb1;                            \
        _Pragma("unroll")                                                     \
        for (int i = 0; i < 4; i++) {                                         \
            hh[i]     = __hmax2(__hadd2(xa0[i], xb0[i]), zero2);              \
            hh[i + 4] = __hmax2(__hadd2(xa1[i], xb1[i]), zero2);              \
        }                                                                     \
        __half* dstA = sAbuf + (stOff) + le * ROWA + lq * 16;                 \
        *(uint4*)dstA       = *(uint4*)&hh[0];                                \
        *(uint4*)(dstA + 8) = *(uint4*)&hh[4];                                \
    } while (0)

#define A_LDG(kchunk)                                                         \
    do {                                                                      \
        const __half* ps = PS + (kchunk) * 32;                                \
        const __half* pr = PR + (kchunk) * 32;                                \
        pa0 = *(const uint4*)ps;       pa1 = *(const uint4*)(ps + 8);         \
        pb0 = *(const uint4*)pr;       pb1 = *(const uint4*)(pr + 8);         \
    } while (0)

    // ---- prologue: chunk0 -> stage0; prefetch chunk1 into regs ----
    A_LDG(0);
    A_RELU_STORE(0);
    A_LDG(1);
    CP_WAIT0();          // B resident ready
    __syncthreads();     // stage0 + B published

    uint32_t stA = 0, stNext = A_STAGE_H, stNext2 = 2 * A_STAGE_H;

    #pragma unroll 1
    for (int kc = 0; kc < NKC; kc++) {
        // store prefetched chunk kc+1; issue LDG for chunk kc+2
        if (kc + 1 < NKC) {
            A_RELU_STORE(stNext);
            int nc = (kc + 2 < NKC) ? (kc + 2) : (NKC - 1);
            A_LDG(nc);
        }
        __syncthreads();   // publish stage (kc+1); stage kc stable for reads

        // ---- MMA on stage kc (A) + resident B ----
        const uint32_t aOff = stA * 2u;
        const uint32_t bK = (uint32_t)(kc * 64);  // bytes: kc*32 halves
        #pragma unroll
        for (int ks = 0; ks < 2; ks++) {
            uint32_t af[4][4];
            #pragma unroll
            for (int mt = 0; mt < 4; mt++)
                ldmx4(af[mt], aBase[mt] + aOff + ks * 32);
            uint32_t bf[4][2];
            {
                uint32_t r[4];
                ldmx4(r, bBase[0] + bK + ks * 32);
                bf[0][0] = r[0]; bf[0][1] = r[1]; bf[1][0] = r[2]; bf[1][1] = r[3];
                ldmx4(r, bBase[1] + bK + ks * 32);
                bf[2][0] = r[0]; bf[2][1] = r[1]; bf[3][0] = r[2]; bf[3][1] = r[3];
            }
            #pragma unroll
            for (int nt = 0; nt < 4; nt++)
                #pragma unroll
                for (int mt = 0; mt < 4; mt++)
                    mma_f16(acc[mt][nt], af[mt], bf[nt]);
        }

        // rotate stages
        uint32_t tmp = stA; stA = stNext; stNext = stNext2; stNext2 = tmp;
    }

    // ---- epilogue (R11): shfl-reduced scatter over sorted receivers ----
    const bool uniform = (s_r[mb] == s_r[mb + 63]);
    if (uniform) {
        float cs[4][2];
        #pragma unroll
        for (int nt = 0; nt < 4; nt++) { cs[nt][0] = 0.0f; cs[nt][1] = 0.0f; }
        #pragma unroll
        for (int mt = 0; mt < 4; mt++) {
            const int row0 = mb + mt * 16 + r4;
            const float w0 = s_relt[row0];
            const float w1 = s_relt[row0 + 8];
            #pragma unroll
            for (int nt = 0; nt < 4; nt++) {
                const int col = nbw + nt * 8 + 2 * c4;
                const float bb0 = s_b2[col];
                const float bb1 = s_b2[col + 1];
                cs[nt][0] += w0 * fmaxf(acc[mt][nt][0] + bb0, 0.0f)
                           + w1 * fmaxf(acc[mt][nt][2] + bb0, 0.0f);
                cs[nt][1] += w0 * fmaxf(acc[mt][nt][1] + bb1, 0.0f)
                           + w1 * fmaxf(acc[mt][nt][3] + bb1, 0.0f);
            }
        }
        #pragma unroll
        for (int off = 4; off < 32; off <<= 1)
            #pragma unroll
            for (int nt = 0; nt < 4; nt++) {
                cs[nt][0] += __shfl_xor_sync(0xFFFFFFFFu, cs[nt][0], off);
                cs[nt][1] += __shfl_xor_sync(0xFFFFFFFFu, cs[nt][1], off);
            }
        if (lane < 4) {
            float* dst = g_agg + (size_t)s_r[mb] * M_N + n0;
            #pragma unroll
            for (int nt = 0; nt < 4; nt++) {
                const int col = nbw + nt * 8 + 2 * c4;
                atomicAdd(dst + col,     cs[nt][0]);
                atomicAdd(dst + col + 1, cs[nt][1]);
            }
        }
    } else {
        #pragma unroll
        for (int mt = 0; mt < 4; mt++) {
            const int row0 = mb + mt * 16 + r4;
            const int row1 = row0 + 8;
            const float w0 = s_relt[row0];
            const float w1 = s_relt[row1];
            float* d0 = g_agg + (size_t)s_r[row0] * M_N + n0;
            float* d1 = g_agg + (size_t)s_r[row1] * M_N + n0;
            #pragma unroll
            for (int nt = 0; nt < 4; nt++) {
                const int col = nbw + nt * 8 + 2 * c4;
                const float bb0 = s_b2[col];
                const float bb1 = s_b2[col + 1];
                atomicAdd(d0 + col,     w0 * fmaxf(acc[mt][nt][0] + bb0, 0.0f));
                atomicAdd(d0 + col + 1, w0 * fmaxf(acc[mt][nt][1] + bb1, 0.0f));
                atomicAdd(d1 + col,     w1 * fmaxf(acc[mt][nt][2] + bb0, 0.0f));
                atomicAdd(d1 + col + 1, w1 * fmaxf(acc[mt][nt][3] + bb1, 0.0f));
            }
        }
    }
#undef A_RELU_STORE
#undef A_LDG
}

// ---------------------------------------------------------------------------
// Launch
// ---------------------------------------------------------------------------
extern "C" void kernel_launch(void* const* d_in, const int* in_sizes, int n_in,
                              void* d_out, int out_size)
{
    const float* inputs = (const float*)d_in[0];
    const float* rel    = (const float*)d_in[1];
    const float* W1     = (const float*)d_in[2];
    const float* b1     = (const float*)d_in[3];
    const float* W2     = (const float*)d_in[4];
    const float* b2     = (const float*)d_in[5];
    const float* Wo1    = (const float*)d_in[6];
    const float* bo1    = (const float*)d_in[7];
    const float* Wo2    = (const float*)d_in[8];
    const float* bo2    = (const float*)d_in[9];
    const float* Wo3    = (const float*)d_in[10];
    const float* bo3    = (const float*)d_in[11];
    const int* send_idx = (const int*)d_in[12];
    const int* rec_idx  = (const int*)d_in[13];
    float* out = (float*)d_out;

    float *pAgg, *pH1, *pH2;
    cudaGetSymbolAddress((void**)&pAgg, g_agg);
    cudaGetSymbolAddress((void**)&pH1, g_h1);
    cudaGetSymbolAddress((void**)&pH2, g_h2);

    cudaFuncSetAttribute(edge_mma_kernel,
                         cudaFuncAttributeMaxDynamicSharedMemorySize, EDGE_SMEM);

    // Prep: weights + projections + receiver sort
    transpose_w2_h<<<dim3(H_N / 32, M_N / 32, 2), dim3(32, 8)>>>(W2);
    layer1_gemm_h<<<dim3(H_N / 64, C_N / 64, 4), 256>>>(inputs, W1, b1);
    zero_kernel<<<(C_N * M_N + 255) / 256, 256>>>();
    hist_kernel<<<128, 512>>>(rec_idx);
    scan_kernel<<<1, 512>>>();
    mkperm_kernel<<<256, 256>>>(rec_idx);

    // Main edge GEMM (type-split, sorted, B-resident, A triple-buffered)
    edge_mma_kernel<<<dim3(E_N / ET, M_N / 128, 2), 512, EDGE_SMEM>>>(
        b2, rel, send_idx, rec_idx);

    // Output MLP (fp32)
    gemm64<<<dim3(OH_N / 64, C_N / 64), 256>>>(pAgg, Wo1, bo1, pH1, M_N, OH_N, 1);
    gemm64<<<dim3(OH_N / 64, C_N / 64), 256>>>(pH1, Wo2, bo2, pH2, OH_N, OH_N, 1);
    gemm64<<<dim3(D_N / 64, C_N / 64), 256>>>(pH2, Wo3, bo3, out, OH_N, D_N, 0);
}

// round 13
// speedup vs baseline: 1.1794x; 1.1794x over previous
#include <cuda_runtime.h>
#include <cuda_fp16.h>
#include <cstdint>

#define C_N 512
#define D_N 256
#define H_N 512
#define M_N 256
#define OH_N 512
#define E_N 261632

// ---------------------------------------------------------------------------
// Device scratch
// ---------------------------------------------------------------------------
__device__ __align__(16) __half g_Ph[4 * C_N * H_N];    // layer-1 projections, fp16
__device__ __align__(16) __half g_W2TH[2 * M_N * H_N];  // W2 transposed [t][n][k], fp16
__device__ __align__(16) float  g_agg[C_N * M_N];
__device__ __align__(16) float  g_h1[C_N * OH_N];
__device__ __align__(16) float  g_h2[C_N * OH_N];
__device__ int g_hist[512];
__device__ int g_cursor[512];
__device__ int g_perm[E_N];
__device__ int g_tileCtr[4];

// ---------------------------------------------------------------------------
// Helpers
// ---------------------------------------------------------------------------
__device__ __forceinline__ uint32_t smem_u32(const void* p) {
    uint32_t a;
    asm("{ .reg .u64 t; cvta.to.shared.u64 t, %1; cvt.u32.u64 %0, t; }" : "=r"(a) : "l"(p));
    return a;
}
__device__ __forceinline__ void cp16(uint32_t dst, const void* src) {
    asm volatile("cp.async.cg.shared.global [%0], [%1], 16;" :: "r"(dst), "l"(src));
}
#define CP_COMMIT() asm volatile("cp.async.commit_group;" ::: "memory")
#define CP_WAIT0()  asm volatile("cp.async.wait_group 0;" ::: "memory")

__device__ __forceinline__ void mma_f16(float* c, const uint32_t* a, const uint32_t* b) {
    asm volatile(
        "mma.sync.aligned.m16n8k16.row.col.f32.f16.f16.f32 "
        "{%0,%1,%2,%3}, {%4,%5,%6,%7}, {%8,%9}, {%0,%1,%2,%3};"
        : "+f"(c[0]), "+f"(c[1]), "+f"(c[2]), "+f"(c[3])
        : "r"(a[0]), "r"(a[1]), "r"(a[2]), "r"(a[3]), "r"(b[0]), "r"(b[1]));
}
__device__ __forceinline__ void ldmx4(uint32_t* r, uint32_t addr) {
    asm volatile("ldmatrix.sync.aligned.m8n8.x4.shared.b16 {%0,%1,%2,%3}, [%4];"
                 : "=r"(r[0]), "=r"(r[1]), "=r"(r[2]), "=r"(r[3]) : "r"(addr));
}

// ---------------------------------------------------------------------------
// fp32 GEMM body (64x64 tile, 256 thr) — proven R2..R12
// ---------------------------------------------------------------------------
__device__ __forceinline__ void gemm64_body(const float* __restrict__ A,
                                            const float* __restrict__ B,
                                            const float* __restrict__ bias,
                                            float* __restrict__ Cf,
                                            __half* __restrict__ Ch,
                                            int K, int N, int doRelu, int m0, int n0)
{
    __shared__ __align__(16) float sA[64][20];
    __shared__ __align__(16) float sB[16][64];

    int tid = threadIdx.x;
    int tx = tid & 15, ty = tid >> 4;
    float acc[4][4] = {};

    for (int k0 = 0; k0 < K; k0 += 16) {
        {
            int row = tid >> 2, cs = (tid & 3) * 4;
            float4 v = *(const float4*)(A + (m0 + row) * K + k0 + cs);
            *(float4*)&sA[row][cs] = v;
        }
        {
            int kk = tid >> 4, cs = (tid & 15) * 4;
            float4 v = *(const float4*)(B + (k0 + kk) * N + n0 + cs);
            *(float4*)&sB[kk][cs] = v;
        }
        __syncthreads();
        #pragma unroll
        for (int k = 0; k < 16; k++) {
            float a[4];
            #pragma unroll
            for (int i = 0; i < 4; i++) a[i] = sA[ty * 4 + i][k];
            float4 bv = *(const float4*)&sB[k][tx * 4];
            #pragma unroll
            for (int i = 0; i < 4; i++) {
                acc[i][0] = fmaf(a[i], bv.x, acc[i][0]);
                acc[i][1] = fmaf(a[i], bv.y, acc[i][1]);
                acc[i][2] = fmaf(a[i], bv.z, acc[i][2]);
                acc[i][3] = fmaf(a[i], bv.w, acc[i][3]);
            }
        }
        __syncthreads();
    }

    #pragma unroll
    for (int i = 0; i < 4; i++) {
        #pragma unroll
        for (int j = 0; j < 4; j++) {
            int n = n0 + tx * 4 + j;
            float v = acc[i][j] + (bias ? bias[n] : 0.0f);
            if (doRelu) v = fmaxf(v, 0.0f);
            if (Cf) Cf[(m0 + ty * 4 + i) * N + n] = v;
            else    Ch[(m0 + ty * 4 + i) * N + n] = __float2half_rn(v);
        }
    }
}

__global__ __launch_bounds__(256, 4)
void gemm64(const float* __restrict__ A, const float* __restrict__ B,
            const float* __restrict__ bias, float* __restrict__ Cmat,
            int K, int N, int doRelu)
{
    gemm64_body(A, B, bias, Cmat, nullptr, K, N, doRelu, blockIdx.y * 64, blockIdx.x * 64);
}

__global__ __launch_bounds__(256, 4)
void layer1_gemm_h(const float* __restrict__ inputs, const float* __restrict__ W1,
                   const float* __restrict__ b1)
{
    int z = blockIdx.z;
    const float* B = W1 + (size_t)z * D_N * H_N;
    const float* bias = ((z & 1) == 0) ? (b1 + (size_t)(z >> 1) * H_N) : nullptr;
    __half* outp = g_Ph + (size_t)z * C_N * H_N;
    gemm64_body(inputs, B, bias, nullptr, outp, D_N, H_N, 0, blockIdx.y * 64, blockIdx.x * 64);
}

__global__ void transpose_w2_h(const float* __restrict__ W2)
{
    __shared__ float tile[32][33];
    int t = blockIdx.z, k0 = blockIdx.x * 32, n0 = blockIdx.y * 32;
    const float* src = W2 + (size_t)t * H_N * M_N;
    __half* dst = g_W2TH + (size_t)t * M_N * H_N;
    #pragma unroll
    for (int i = 0; i < 4; i++)
        tile[threadIdx.y + i * 8][threadIdx.x] =
            src[(size_t)(k0 + threadIdx.y + i * 8) * M_N + n0 + threadIdx.x];
    __syncthreads();
    #pragma unroll
    for (int i = 0; i < 4; i++)
        dst[(size_t)(n0 + threadIdx.y + i * 8) * H_N + k0 + threadIdx.x] =
            __float2half_rn(tile[threadIdx.x][threadIdx.y + i * 8]);
}

// ---------------------------------------------------------------------------
// Counting sort of edges by receiver (proven R7/R11)
// ---------------------------------------------------------------------------
__global__ void zero_kernel()
{
    int i = blockIdx.x * blockDim.x + threadIdx.x;
    if (i < C_N * M_N) g_agg[i] = 0.0f;
    if (i < 512) g_hist[i] = 0;
    if (i < 4) g_tileCtr[i] = 0;
}

__global__ __launch_bounds__(512)
void hist_kernel(const int* __restrict__ rec)
{
    __shared__ int h[512];
    int tid = threadIdx.x;
    h[tid] = 0;
    __syncthreads();
    for (int e = blockIdx.x * 512 + tid; e < E_N; e += gridDim.x * 512)
        atomicAdd(&h[rec[e]], 1);
    __syncthreads();
    atomicAdd(&g_hist[tid], h[tid]);
}

__global__ __launch_bounds__(512)
void scan_kernel()
{
    __shared__ int tmp[2][512];
    int tid = threadIdx.x;
    int v = g_hist[tid];
    tmp[0][tid] = v;
    __syncthreads();
    int src = 0;
    for (int off = 1; off < 512; off <<= 1) {
        int val = tmp[src][tid];
        if (tid >= off) val += tmp[src][tid - off];
        tmp[src ^ 1][tid] = val;
        src ^= 1;
        __syncthreads();
    }
    g_cursor[tid] = tmp[src][tid] - v;   // exclusive prefix
}

__global__ __launch_bounds__(256)
void mkperm_kernel(const int* __restrict__ rec)
{
    for (int e = blockIdx.x * blockDim.x + threadIdx.x; e < E_N;
         e += gridDim.x * blockDim.x) {
        int c = rec[e];
        int pos = atomicAdd(&g_cursor[c], 1);
        g_perm[pos] = e;
    }
}

// ---------------------------------------------------------------------------
// Edge kernel v9: PERSISTENT CTAs. grid (152, 4). Class = blockIdx.y encodes
// (type, n0-half); B for the class loaded ONCE into resident smem (133KB).
// Each CTA dynamically steals 256-edge tiles (per-class atomic counter) and
// runs R11's inner loop: A double-buffered via reg prefetch, ldmatrix frags,
// one sync per kc, shfl-reduced sorted scatter.
// ---------------------------------------------------------------------------
#define ET 256
#define ROWA 40
#define ROWB 520
#define A_STAGE_H (ET * ROWA)        // 10240 halves (20KB)
#define B_FULL_H  (128 * ROWB)       // 66560 halves (133KB)
#define NKC (H_N / 32)               // 16
#define NTILES (E_N / ET)            // 1022
#define EDGE_SMEM ((B_FULL_H + 2 * A_STAGE_H) * 2)   // 174080 B

__global__ __launch_bounds__(512, 1)
void edge_mma_kernel(const float* __restrict__ b2, const float* __restrict__ rel,
                     const int* __restrict__ send, const int* __restrict__ rec)
{
    extern __shared__ __align__(16) __half dsm[];
    __half* sBfull = dsm;                      // [128][ROWB] resident
    __half* sAbuf  = dsm + B_FULL_H;           // 2 stages [ET][ROWA]
    __shared__ float s_relt[ET];
    __shared__ int   s_r[ET];
    __shared__ int   s_p[ET];
    __shared__ float s_b2[128];
    __shared__ int   s_tile;

    const int tid  = threadIdx.x;
    const int lane = tid & 31;
    const int warp = tid >> 5;
    const int mb  = (warp & 3) * 64;      // 64-edge strip
    const int nbw = (warp >> 2) * 32;     // 32-col strip
    const int cls = blockIdx.y;           // 0..3
    const int t   = cls >> 1;
    const int n0  = (cls & 1) * 128;
    const int r4 = lane >> 2, c4 = lane & 3;

    const uint32_t sB_u32 = smem_u32(sBfull);
    const uint32_t sA_u32 = smem_u32(sAbuf);

    // ---- B resident load (once per CTA) ----
    {
        const int row = tid >> 2;
        const int bq = tid & 3;
        const __half* src = g_W2TH + ((size_t)t * M_N + n0 + row) * H_N + bq * 128;
        uint32_t d = sB_u32 + (uint32_t)(row * ROWB + bq * 128) * 2u;
        #pragma unroll
        for (int j = 0; j < 16; j++)
            cp16(d + j * 16, src + j * 8);
        CP_COMMIT();
    }
    if (tid < 128) s_b2[tid] = b2[t * M_N + n0 + tid];

    // ldmatrix per-lane base addresses (bytes) — fixed for the whole kernel
    const int lrA = lane & 15;
    const int khA = (lane >> 4) * 8;
    const int lrB = ((lane >> 4) & 1) * 8 + (lane & 7);
    const int khB = ((lane >> 3) & 1) * 8;
    uint32_t aBase[4], bBase[2];
    #pragma unroll
    for (int mt = 0; mt < 4; mt++)
        aBase[mt] = sA_u32 + (uint32_t)((mb + mt * 16 + lrA) * ROWA + khA) * 2u;
    #pragma unroll
    for (int p = 0; p < 2; p++)
        bBase[p] = sB_u32 + (uint32_t)((nbw + p * 16 + lrB) * ROWB + khB) * 2u;

    const int le = tid >> 1;
    const int lq = tid & 1;
    const __half2 zero2 = __float2half2_rn(0.0f);

    CP_WAIT0();   // B resident complete (visibility sealed by first barrier)

    // ---- persistent tile loop ----
    for (;;) {
        if (tid == 0) s_tile = atomicAdd(&g_tileCtr[cls], 1);
        __syncthreads();   // publishes s_tile; also protects s_* reuse
        const int tile = s_tile;
        if (tile >= NTILES) break;
        const int e0 = tile * ET;

        if (tid < ET) {
            int p = g_perm[e0 + tid];
            s_p[tid] = p;
            s_r[tid] = rec[p];
            s_relt[tid] = rel[(size_t)p * 2 + t];
        }
        __syncthreads();

        const int sn = send[s_p[le]];
        const int rn = s_r[le];
        const __half* PS = g_Ph + ((size_t)(t * 2 + 0) * C_N + sn) * H_N + lq * 16;
        const __half* PR = g_Ph + ((size_t)(t * 2 + 1) * C_N + rn) * H_N + lq * 16;

        float acc[4][4][4];
        #pragma unroll
        for (int i = 0; i < 4; i++)
            #pragma unroll
            for (int j = 0; j < 4; j++)
                #pragma unroll
                for (int q = 0; q < 4; q++) acc[i][j][q] = 0.0f;

        uint4 pa0, pa1, pb0, pb1;

#define A_LDG(kchunk)                                                         \
    do {                                                                      \
        const __half* ps = PS + (kchunk) * 32;                                \
        const __half* pr = PR + (kchunk) * 32;                                \
        pa0 = *(const uint4*)ps;       pa1 = *(const uint4*)(ps + 8);         \
        pb0 = *(const uint4*)pr;       pb1 = *(const uint4*)(pr + 8);         \
    } while (0)

#define A_RELU_STORE(stOff)                                                   \
    do {                                                                      \
        __half2 hh[8];                                                        \
        const __half2* xa0 = (const __half2*)&pa0;                            \
        const __half2* xa1 = (const __half2*)&pa1;                            \
        const __half2* xb0 = (const __half2*)&pb0;                            \
        const __half2* xb1 = (const __half2*)&pb1;                            \
        _Pragma("unroll")                                                     \
        for (int i = 0; i < 4; i++) {                                         \
            hh[i]     = __hmax2(__hadd2(xa0[i], xb0[i]), zero2);              \
            hh[i + 4] = __hmax2(__hadd2(xa1[i], xb1[i]), zero2);              \
        }                                                                     \
        __half* dstA = sAbuf + (stOff) + le * ROWA + lq * 16;                 \
        *(uint4*)dstA       = *(uint4*)&hh[0];                                \
        *(uint4*)(dstA + 8) = *(uint4*)&hh[4];                                \
    } while (0)

        // ---- A prologue: chunk0 -> stage0 ----
        A_LDG(0);
        A_RELU_STORE(0);
        __syncthreads();

        #pragma unroll 1
        for (int kc = 0; kc < NKC; kc++) {
            const int cur = kc & 1;
            const bool more = (kc + 1 < NKC);
            if (more) A_LDG(kc + 1);   // prefetch next A into regs

            // ---- MMA on stage cur (A) + resident B ----
            const uint32_t aOff = (uint32_t)(cur * A_STAGE_H) * 2u;
            const uint32_t bK = (uint32_t)(kc * 64);   // bytes (kc*32 halves)
            #pragma unroll
            for (int ks = 0; ks < 2; ks++) {
                uint32_t af[4][4];
                #pragma unroll
                for (int mt = 0; mt < 4; mt++)
                    ldmx4(af[mt], aBase[mt] + aOff + ks * 32);
                uint32_t bf[4][2];
                {
                    uint32_t r[4];
                    ldmx4(r, bBase[0] + bK + ks * 32);
                    bf[0][0] = r[0]; bf[0][1] = r[1]; bf[1][0] = r[2]; bf[1][1] = r[3];
                    ldmx4(r, bBase[1] + bK + ks * 32);
                    bf[2][0] = r[0]; bf[2][1] = r[1]; bf[3][0] = r[2]; bf[3][1] = r[3];
                }
                #pragma unroll
                for (int nt = 0; nt < 4; nt++)
                    #pragma unroll
                    for (int mt = 0; mt < 4; mt++)
                        mma_f16(acc[mt][nt], af[mt], bf[nt]);
            }

            if (more) A_RELU_STORE((cur ^ 1) * A_STAGE_H);
            __syncthreads();
        }
#undef A_LDG
#undef A_RELU_STORE

        // ---- epilogue: shfl-reduced scatter over sorted receivers ----
        const bool uniform = (s_r[mb] == s_r[mb + 63]);
        if (uniform) {
            float cs[4][2];
            #pragma unroll
            for (int nt = 0; nt < 4; nt++) { cs[nt][0] = 0.0f; cs[nt][1] = 0.0f; }
            #pragma unroll
            for (int mt = 0; mt < 4; mt++) {
                const int row0 = mb + mt * 16 + r4;
                const float w0 = s_relt[row0];
                const float w1 = s_relt[row0 + 8];
                #pragma unroll
                for (int nt = 0; nt < 4; nt++) {
                    const int col = nbw + nt * 8 + 2 * c4;
                    const float bb0 = s_b2[col];
                    const float bb1 = s_b2[col + 1];
                    cs[nt][0] += w0 * fmaxf(acc[mt][nt][0] + bb0, 0.0f)
                               + w1 * fmaxf(acc[mt][nt][2] + bb0, 0.0f);
                    cs[nt][1] += w0 * fmaxf(acc[mt][nt][1] + bb1, 0.0f)
                               + w1 * fmaxf(acc[mt][nt][3] + bb1, 0.0f);
                }
            }
            #pragma unroll
            for (int off = 4; off < 32; off <<= 1)
                #pragma unroll
                for (int nt = 0; nt < 4; nt++) {
                    cs[nt][0] += __shfl_xor_sync(0xFFFFFFFFu, cs[nt][0], off);
                    cs[nt][1] += __shfl_xor_sync(0xFFFFFFFFu, cs[nt][1], off);
                }
            if (lane < 4) {
                float* dst = g_agg + (size_t)s_r[mb] * M_N + n0;
                #pragma unroll
                for (int nt = 0; nt < 4; nt++) {
                    const int col = nbw + nt * 8 + 2 * c4;
                    atomicAdd(dst + col,     cs[nt][0]);
                    atomicAdd(dst + col + 1, cs[nt][1]);
                }
            }
        } else {
            #pragma unroll
            for (int mt = 0; mt < 4; mt++) {
                const int row0 = mb + mt * 16 + r4;
                const int row1 = row0 + 8;
                const float w0 = s_relt[row0];
                const float w1 = s_relt[row1];
                float* d0 = g_agg + (size_t)s_r[row0] * M_N + n0;
                float* d1 = g_agg + (size_t)s_r[row1] * M_N + n0;
                #pragma unroll
                for (int nt = 0; nt < 4; nt++) {
                    const int col = nbw + nt * 8 + 2 * c4;
                    const float bb0 = s_b2[col];
                    const float bb1 = s_b2[col + 1];
                    atomicAdd(d0 + col,     w0 * fmaxf(acc[mt][nt][0] + bb0, 0.0f));
                    atomicAdd(d0 + col + 1, w0 * fmaxf(acc[mt][nt][1] + bb1, 0.0f));
                    atomicAdd(d1 + col,     w1 * fmaxf(acc[mt][nt][2] + bb0, 0.0f));
                    atomicAdd(d1 + col + 1, w1 * fmaxf(acc[mt][nt][3] + bb1, 0.0f));
                }
            }
        }
    }
}

// ---------------------------------------------------------------------------
// Launch
// ---------------------------------------------------------------------------
extern "C" void kernel_launch(void* const* d_in, const int* in_sizes, int n_in,
                              void* d_out, int out_size)
{
    const float* inputs = (const float*)d_in[0];
    const float* rel    = (const float*)d_in[1];
    const float* W1     = (const float*)d_in[2];
    const float* b1     = (const float*)d_in[3];
    const float* W2     = (const float*)d_in[4];
    const float* b2     = (const float*)d_in[5];
    const float* Wo1    = (const float*)d_in[6];
    const float* bo1    = (const float*)d_in[7];
    const float* Wo2    = (const float*)d_in[8];
    const float* bo2    = (const float*)d_in[9];
    const float* Wo3    = (const float*)d_in[10];
    const float* bo3    = (const float*)d_in[11];
    const int* send_idx = (const int*)d_in[12];
    const int* rec_idx  = (const int*)d_in[13];
    float* out = (float*)d_out;

    float *pAgg, *pH1, *pH2;
    cudaGetSymbolAddress((void**)&pAgg, g_agg);
    cudaGetSymbolAddress((void**)&pH1, g_h1);
    cudaGetSymbolAddress((void**)&pH2, g_h2);

    cudaFuncSetAttribute(edge_mma_kernel,
                         cudaFuncAttributeMaxDynamicSharedMemorySize, EDGE_SMEM);

    // Prep: weights + projections + receiver sort (+ tile counters reset)
    transpose_w2_h<<<dim3(H_N / 32, M_N / 32, 2), dim3(32, 8)>>>(W2);
    layer1_gemm_h<<<dim3(H_N / 64, C_N / 64, 4), 256>>>(inputs, W1, b1);
    zero_kernel<<<(C_N * M_N + 255) / 256, 256>>>();
    hist_kernel<<<128, 512>>>(rec_idx);
    scan_kernel<<<1, 512>>>();
    mkperm_kernel<<<256, 256>>>(rec_idx);

    // Main edge GEMM: persistent CTAs, B resident per class, dynamic tiles
    edge_mma_kernel<<<dim3(152, 4), 512, EDGE_SMEM>>>(
        b2, rel, send_idx, rec_idx);

    // Output MLP (fp32)
    gemm64<<<dim3(OH_N / 64, C_N / 64), 256>>>(pAgg, Wo1, bo1, pH1, M_N, OH_N, 1);
    gemm64<<<dim3(OH_N / 64, C_N / 64), 256>>>(pH1, Wo2, bo2, pH2, OH_N, OH_N, 1);
    gemm64<<<dim3(D_N / 64, C_N / 64), 256>>>(pH2, Wo3, bo3, out, OH_N, D_N, 0);
}

// round 14
// speedup vs baseline: 1.1971x; 1.0150x over previous
#include <cuda_runtime.h>
#include <cuda_fp16.h>
#include <cstdint>

#define C_N 512
#define D_N 256
#define H_N 512
#define M_N 256
#define OH_N 512
#define E_N 261632

// ---------------------------------------------------------------------------
// Device scratch
// ---------------------------------------------------------------------------
__device__ __align__(16) __half g_Ph[4 * C_N * H_N];    // layer-1 projections, fp16
__device__ __align__(16) __half g_W2TH[2 * M_N * H_N];  // W2 transposed [t][n][k], fp16
__device__ __align__(16) float  g_agg[C_N * M_N];
__device__ __align__(16) float  g_h1[C_N * OH_N];
__device__ __align__(16) float  g_h2[C_N * OH_N];
__device__ int g_hist[512];
__device__ int g_cursor[512];
__device__ int g_perm[E_N];
__device__ int g_tileCtr[4];

// ---------------------------------------------------------------------------
// Helpers
// ---------------------------------------------------------------------------
__device__ __forceinline__ uint32_t smem_u32(const void* p) {
    uint32_t a;
    asm("{ .reg .u64 t; cvta.to.shared.u64 t, %1; cvt.u32.u64 %0, t; }" : "=r"(a) : "l"(p));
    return a;
}
__device__ __forceinline__ void cp16(uint32_t dst, const void* src) {
    asm volatile("cp.async.cg.shared.global [%0], [%1], 16;" :: "r"(dst), "l"(src));
}
#define CP_COMMIT() asm volatile("cp.async.commit_group;" ::: "memory")
#define CP_WAIT0()  asm volatile("cp.async.wait_group 0;" ::: "memory")

__device__ __forceinline__ void mma_f16(float* c, const uint32_t* a, const uint32_t* b) {
    asm volatile(
        "mma.sync.aligned.m16n8k16.row.col.f32.f16.f16.f32 "
        "{%0,%1,%2,%3}, {%4,%5,%6,%7}, {%8,%9}, {%0,%1,%2,%3};"
        : "+f"(c[0]), "+f"(c[1]), "+f"(c[2]), "+f"(c[3])
        : "r"(a[0]), "r"(a[1]), "r"(a[2]), "r"(a[3]), "r"(b[0]), "r"(b[1]));
}
__device__ __forceinline__ void ldmx4(uint32_t* r, uint32_t addr) {
    asm volatile("ldmatrix.sync.aligned.m8n8.x4.shared.b16 {%0,%1,%2,%3}, [%4];"
                 : "=r"(r[0]), "=r"(r[1]), "=r"(r[2]), "=r"(r[3]) : "r"(addr));
}

// ---------------------------------------------------------------------------
// fp32 GEMM, 32x64 tile, BK=32, 256 thr (2x CTAs + half barriers vs gemm64)
// ---------------------------------------------------------------------------
__device__ __forceinline__ void gemm32_body(const float* __restrict__ A,
                                            const float* __restrict__ B,
                                            const float* __restrict__ bias,
                                            float* __restrict__ Cf,
                                            __half* __restrict__ Ch,
                                            int K, int N, int doRelu, int m0, int n0)
{
    __shared__ __align__(16) float sA[32][36];
    __shared__ __align__(16) float sB[32][68];

    int tid = threadIdx.x;
    int tx = tid & 15, ty = tid >> 4;
    float acc[2][4] = {};

    for (int k0 = 0; k0 < K; k0 += 32) {
        {
            int row = tid >> 3, cs = (tid & 7) * 4;
            float4 v = *(const float4*)(A + (size_t)(m0 + row) * K + k0 + cs);
            *(float4*)&sA[row][cs] = v;
        }
        {
            int kk = tid >> 3, cs = (tid & 7) * 8;
            const float* src = B + (size_t)(k0 + kk) * N + n0 + cs;
            float4 v0 = *(const float4*)(src);
            float4 v1 = *(const float4*)(src + 4);
            *(float4*)&sB[kk][cs]     = v0;
            *(float4*)&sB[kk][cs + 4] = v1;
        }
        __syncthreads();
        #pragma unroll
        for (int k = 0; k < 32; k++) {
            float a0 = sA[ty * 2][k];
            float a1 = sA[ty * 2 + 1][k];
            float4 bv = *(const float4*)&sB[k][tx * 4];
            acc[0][0] = fmaf(a0, bv.x, acc[0][0]);
            acc[0][1] = fmaf(a0, bv.y, acc[0][1]);
            acc[0][2] = fmaf(a0, bv.z, acc[0][2]);
            acc[0][3] = fmaf(a0, bv.w, acc[0][3]);
            acc[1][0] = fmaf(a1, bv.x, acc[1][0]);
            acc[1][1] = fmaf(a1, bv.y, acc[1][1]);
            acc[1][2] = fmaf(a1, bv.z, acc[1][2]);
            acc[1][3] = fmaf(a1, bv.w, acc[1][3]);
        }
        __syncthreads();
    }

    #pragma unroll
    for (int i = 0; i < 2; i++) {
        #pragma unroll
        for (int j = 0; j < 4; j++) {
            int n = n0 + tx * 4 + j;
            float v = acc[i][j] + (bias ? bias[n] : 0.0f);
            if (doRelu) v = fmaxf(v, 0.0f);
            if (Cf) Cf[(size_t)(m0 + ty * 2 + i) * N + n] = v;
            else    Ch[(size_t)(m0 + ty * 2 + i) * N + n] = __float2half_rn(v);
        }
    }
}

__global__ __launch_bounds__(256, 6)
void gemm32(const float* __restrict__ A, const float* __restrict__ B,
            const float* __restrict__ bias, float* __restrict__ Cmat,
            int K, int N, int doRelu)
{
    gemm32_body(A, B, bias, Cmat, nullptr, K, N, doRelu, blockIdx.y * 32, blockIdx.x * 64);
}

// Layer-1: 4 (type, part) projections -> fp16 P, one launch
__global__ __launch_bounds__(256, 6)
void layer1_gemm_h(const float* __restrict__ inputs, const float* __restrict__ W1,
                   const float* __restrict__ b1)
{
    int z = blockIdx.z;
    const float* B = W1 + (size_t)z * D_N * H_N;
    const float* bias = ((z & 1) == 0) ? (b1 + (size_t)(z >> 1) * H_N) : nullptr;
    __half* outp = g_Ph + (size_t)z * C_N * H_N;
    gemm32_body(inputs, B, bias, nullptr, outp, D_N, H_N, 0,
                blockIdx.y * 32, blockIdx.x * 64);
}

// W2 transpose (+ folded zeroing of agg/hist/tileCtr)
__global__ void transpose_w2_h(const float* __restrict__ W2)
{
    __shared__ float tile[32][33];
    int t = blockIdx.z, k0 = blockIdx.x * 32, n0 = blockIdx.y * 32;
    const float* src = W2 + (size_t)t * H_N * M_N;
    __half* dst = g_W2TH + (size_t)t * M_N * H_N;
    int tid = threadIdx.y * 32 + threadIdx.x;

    // folded zeroing (grid = 16*8*2 = 256 blocks x 256 thr = 65536 threads)
    {
        int bid = (blockIdx.z * gridDim.y + blockIdx.y) * gridDim.x + blockIdx.x;
        int gid = bid * 256 + tid;
        for (int i = gid; i < C_N * M_N; i += 65536) g_agg[i] = 0.0f;
        if (gid < 512) g_hist[gid] = 0;
        if (gid < 4)   g_tileCtr[gid] = 0;
    }

    #pragma unroll
    for (int i = 0; i < 4; i++)
        tile[threadIdx.y + i * 8][threadIdx.x] =
            src[(size_t)(k0 + threadIdx.y + i * 8) * M_N + n0 + threadIdx.x];
    __syncthreads();
    #pragma unroll
    for (int i = 0; i < 4; i++)
        dst[(size_t)(n0 + threadIdx.y + i * 8) * H_N + k0 + threadIdx.x] =
            __float2half_rn(tile[threadIdx.x][threadIdx.y + i * 8]);
}

// ---------------------------------------------------------------------------
// Counting sort of edges by receiver (proven R7/R11/R13)
// ---------------------------------------------------------------------------
__global__ __launch_bounds__(512)
void hist_kernel(const int* __restrict__ rec)
{
    __shared__ int h[512];
    int tid = threadIdx.x;
    h[tid] = 0;
    __syncthreads();
    for (int e = blockIdx.x * 512 + tid; e < E_N; e += gridDim.x * 512)
        atomicAdd(&h[rec[e]], 1);
    __syncthreads();
    atomicAdd(&g_hist[tid], h[tid]);
}

__global__ __launch_bounds__(512)
void scan_kernel()
{
    __shared__ int tmp[2][512];
    int tid = threadIdx.x;
    int v = g_hist[tid];
    tmp[0][tid] = v;
    __syncthreads();
    int src = 0;
    for (int off = 1; off < 512; off <<= 1) {
        int val = tmp[src][tid];
        if (tid >= off) val += tmp[src][tid - off];
        tmp[src ^ 1][tid] = val;
        src ^= 1;
        __syncthreads();
    }
    g_cursor[tid] = tmp[src][tid] - v;   // exclusive prefix
}

__global__ __launch_bounds__(256)
void mkperm_kernel(const int* __restrict__ rec)
{
    for (int e = blockIdx.x * blockDim.x + threadIdx.x; e < E_N;
         e += gridDim.x * blockDim.x) {
        int c = rec[e];
        int pos = atomicAdd(&g_cursor[c], 1);
        g_perm[pos] = e;
    }
}

// ---------------------------------------------------------------------------
// Edge kernel v9 (R13, unchanged): PERSISTENT CTAs, grid (152, 4).
// Class = (type, n0-half); B resident in smem (133KB, loaded once).
// Dynamic 256-edge tile stealing; A double-buffered via reg prefetch;
// ldmatrix fragments; one sync per kc; shfl-reduced sorted scatter.
// ---------------------------------------------------------------------------
#define ET 256
#define ROWA 40
#define ROWB 520
#define A_STAGE_H (ET * ROWA)        // 10240 halves (20KB)
#define B_FULL_H  (128 * ROWB)       // 66560 halves (133KB)
#define NKC (H_N / 32)               // 16
#define NTILES (E_N / ET)            // 1022
#define EDGE_SMEM ((B_FULL_H + 2 * A_STAGE_H) * 2)   // 174080 B

__global__ __launch_bounds__(512, 1)
void edge_mma_kernel(const float* __restrict__ b2, const float* __restrict__ rel,
                     const int* __restrict__ send, const int* __restrict__ rec)
{
    extern __shared__ __align__(16) __half dsm[];
    __half* sBfull = dsm;                      // [128][ROWB] resident
    __half* sAbuf  = dsm + B_FULL_H;           // 2 stages [ET][ROWA]
    __shared__ float s_relt[ET];
    __shared__ int   s_r[ET];
    __shared__ int   s_p[ET];
    __shared__ float s_b2[128];
    __shared__ int   s_tile;

    const int tid  = threadIdx.x;
    const int lane = tid & 31;
    const int warp = tid >> 5;
    const int mb  = (warp & 3) * 64;      // 64-edge strip
    const int nbw = (warp >> 2) * 32;     // 32-col strip
    const int cls = blockIdx.y;           // 0..3
    const int t   = cls >> 1;
    const int n0  = (cls & 1) * 128;
    const int r4 = lane >> 2, c4 = lane & 3;

    const uint32_t sB_u32 = smem_u32(sBfull);
    const uint32_t sA_u32 = smem_u32(sAbuf);

    // ---- B resident load (once per CTA) ----
    {
        const int row = tid >> 2;
        const int bq = tid & 3;
        const __half* src = g_W2TH + ((size_t)t * M_N + n0 + row) * H_N + bq * 128;
        uint32_t d = sB_u32 + (uint32_t)(row * ROWB + bq * 128) * 2u;
        #pragma unroll
        for (int j = 0; j < 16; j++)
            cp16(d + j * 16, src + j * 8);
        CP_COMMIT();
    }
    if (tid < 128) s_b2[tid] = b2[t * M_N + n0 + tid];

    // ldmatrix per-lane base addresses (bytes) — fixed for the whole kernel
    const int lrA = lane & 15;
    const int khA = (lane >> 4) * 8;
    const int lrB = ((lane >> 4) & 1) * 8 + (lane & 7);
    const int khB = ((lane >> 3) & 1) * 8;
    uint32_t aBase[4], bBase[2];
    #pragma unroll
    for (int mt = 0; mt < 4; mt++)
        aBase[mt] = sA_u32 + (uint32_t)((mb + mt * 16 + lrA) * ROWA + khA) * 2u;
    #pragma unroll
    for (int p = 0; p < 2; p++)
        bBase[p] = sB_u32 + (uint32_t)((nbw + p * 16 + lrB) * ROWB + khB) * 2u;

    const int le = tid >> 1;
    const int lq = tid & 1;
    const __half2 zero2 = __float2half2_rn(0.0f);

    CP_WAIT0();   // B resident complete (visibility sealed by first barrier)

    // ---- persistent tile loop ----
    for (;;) {
        if (tid == 0) s_tile = atomicAdd(&g_tileCtr[cls], 1);
        __syncthreads();   // publishes s_tile; also protects s_* reuse
        const int tile = s_tile;
        if (tile >= NTILES) break;
        const int e0 = tile * ET;

        if (tid < ET) {
            int p = g_perm[e0 + tid];
            s_p[tid] = p;
            s_r[tid] = rec[p];
            s_relt[tid] = rel[(size_t)p * 2 + t];
        }
        __syncthreads();

        const int sn = send[s_p[le]];
        const int rn = s_r[le];
        const __half* PS = g_Ph + ((size_t)(t * 2 + 0) * C_N + sn) * H_N + lq * 16;
        const __half* PR = g_Ph + ((size_t)(t * 2 + 1) * C_N + rn) * H_N + lq * 16;

        float acc[4][4][4];
        #pragma unroll
        for (int i = 0; i < 4; i++)
            #pragma unroll
            for (int j = 0; j < 4; j++)
                #pragma unroll
                for (int q = 0; q < 4; q++) acc[i][j][q] = 0.0f;

        uint4 pa0, pa1, pb0, pb1;

#define A_LDG(kchunk)                                                         \
    do {                                                                      \
        const __half* ps = PS + (kchunk) * 32;                                \
        const __half* pr = PR + (kchunk) * 32;                                \
        pa0 = *(const uint4*)ps;       pa1 = *(const uint4*)(ps + 8);         \
        pb0 = *(const uint4*)pr;       pb1 = *(const uint4*)(pr + 8);         \
    } while (0)

#define A_RELU_STORE(stOff)                                                   \
    do {                                                                      \
        __half2 hh[8];                                                        \
        const __half2* xa0 = (const __half2*)&pa0;                            \
        const __half2* xa1 = (const __half2*)&pa1;                            \
        const __half2* xb0 = (const __half2*)&pb0;                            \
        const __half2* xb1 = (const __half2*)&pb1;                            \
        _Pragma("unroll")                                                     \
        for (int i = 0; i < 4; i++) {                                         \
            hh[i]     = __hmax2(__hadd2(xa0[i], xb0[i]), zero2);              \
            hh[i + 4] = __hmax2(__hadd2(xa1[i], xb1[i]), zero2);              \
        }                                                                     \
        __half* dstA = sAbuf + (stOff) + le * ROWA + lq * 16;                 \
        *(uint4*)dstA       = *(uint4*)&hh[0];                                \
        *(uint4*)(dstA + 8) = *(uint4*)&hh[4];                                \
    } while (0)

        // ---- A prologue: chunk0 -> stage0 ----
        A_LDG(0);
        A_RELU_STORE(0);
        __syncthreads();

        #pragma unroll 1
        for (int kc = 0; kc < NKC; kc++) {
            const int cur = kc & 1;
            const bool more = (kc + 1 < NKC);
            if (more) A_LDG(kc + 1);   // prefetch next A into regs

            // ---- MMA on stage cur (A) + resident B ----
            const uint32_t aOff = (uint32_t)(cur * A_STAGE_H) * 2u;
            const uint32_t bK = (uint32_t)(kc * 64);   // bytes (kc*32 halves)
            #pragma unroll
            for (int ks = 0; ks < 2; ks++) {
                uint32_t af[4][4];
                #pragma unroll
                for (int mt = 0; mt < 4; mt++)
                    ldmx4(af[mt], aBase[mt] + aOff + ks * 32);
                uint32_t bf[4][2];
                {
                    uint32_t r[4];
                    ldmx4(r, bBase[0] + bK + ks * 32);
                    bf[0][0] = r[0]; bf[0][1] = r[1]; bf[1][0] = r[2]; bf[1][1] = r[3];
                    ldmx4(r, bBase[1] + bK + ks * 32);
                    bf[2][0] = r[0]; bf[2][1] = r[1]; bf[3][0] = r[2]; bf[3][1] = r[3];
                }
                #pragma unroll
                for (int nt = 0; nt < 4; nt++)
                    #pragma unroll
                    for (int mt = 0; mt < 4; mt++)
                        mma_f16(acc[mt][nt], af[mt], bf[nt]);
            }

            if (more) A_RELU_STORE((cur ^ 1) * A_STAGE_H);
            __syncthreads();
        }
#undef A_LDG
#undef A_RELU_STORE

        // ---- epilogue: shfl-reduced scatter over sorted receivers ----
        const bool uniform = (s_r[mb] == s_r[mb + 63]);
        if (uniform) {
            float cs[4][2];
            #pragma unroll
            for (int nt = 0; nt < 4; nt++) { cs[nt][0] = 0.0f; cs[nt][1] = 0.0f; }
            #pragma unroll
            for (int mt = 0; mt < 4; mt++) {
                const int row0 = mb + mt * 16 + r4;
                const float w0 = s_relt[row0];
                const float w1 = s_relt[row0 + 8];
                #pragma unroll
                for (int nt = 0; nt < 4; nt++) {
                    const int col = nbw + nt * 8 + 2 * c4;
                    const float bb0 = s_b2[col];
                    const float bb1 = s_b2[col + 1];
                    cs[nt][0] += w0 * fmaxf(acc[mt][nt][0] + bb0, 0.0f)
                               + w1 * fmaxf(acc[mt][nt][2] + bb0, 0.0f);
                    cs[nt][1] += w0 * fmaxf(acc[mt][nt][1] + bb1, 0.0f)
                               + w1 * fmaxf(acc[mt][nt][3] + bb1, 0.0f);
                }
            }
            #pragma unroll
            for (int off = 4; off < 32; off <<= 1)
                #pragma unroll
                for (int nt = 0; nt < 4; nt++) {
                    cs[nt][0] += __shfl_xor_sync(0xFFFFFFFFu, cs[nt][0], off);
                    cs[nt][1] += __shfl_xor_sync(0xFFFFFFFFu, cs[nt][1], off);
                }
            if (lane < 4) {
                float* dst = g_agg + (size_t)s_r[mb] * M_N + n0;
                #pragma unroll
                for (int nt = 0; nt < 4; nt++) {
                    const int col = nbw + nt * 8 + 2 * c4;
                    atomicAdd(dst + col,     cs[nt][0]);
                    atomicAdd(dst + col + 1, cs[nt][1]);
                }
            }
        } else {
            #pragma unroll
            for (int mt = 0; mt < 4; mt++) {
                const int row0 = mb + mt * 16 + r4;
                const int row1 = row0 + 8;
                const float w0 = s_relt[row0];
                const float w1 = s_relt[row1];
                float* d0 = g_agg + (size_t)s_r[row0] * M_N + n0;
                float* d1 = g_agg + (size_t)s_r[row1] * M_N + n0;
                #pragma unroll
                for (int nt = 0; nt < 4; nt++) {
                    const int col = nbw + nt * 8 + 2 * c4;
                    const float bb0 = s_b2[col];
                    const float bb1 = s_b2[col + 1];
                    atomicAdd(d0 + col,     w0 * fmaxf(acc[mt][nt][0] + bb0, 0.0f));
                    atomicAdd(d0 + col + 1, w0 * fmaxf(acc[mt][nt][1] + bb1, 0.0f));
                    atomicAdd(d1 + col,     w1 * fmaxf(acc[mt][nt][2] + bb0, 0.0f));
                    atomicAdd(d1 + col + 1, w1 * fmaxf(acc[mt][nt][3] + bb1, 0.0f));
                }
            }
        }
    }
}

// ---------------------------------------------------------------------------
// Launch
// ---------------------------------------------------------------------------
extern "C" void kernel_launch(void* const* d_in, const int* in_sizes, int n_in,
                              void* d_out, int out_size)
{
    const float* inputs = (const float*)d_in[0];
    const float* rel    = (const float*)d_in[1];
    const float* W1     = (const float*)d_in[2];
    const float* b1     = (const float*)d_in[3];
    const float* W2     = (const float*)d_in[4];
    const float* b2     = (const float*)d_in[5];
    const float* Wo1    = (const float*)d_in[6];
    const float* bo1    = (const float*)d_in[7];
    const float* Wo2    = (const float*)d_in[8];
    const float* bo2    = (const float*)d_in[9];
    const float* Wo3    = (const float*)d_in[10];
    const float* bo3    = (const float*)d_in[11];
    const int* send_idx = (const int*)d_in[12];
    const int* rec_idx  = (const int*)d_in[13];
    float* out = (float*)d_out;

    float *pAgg, *pH1, *pH2;
    cudaGetSymbolAddress((void**)&pAgg, g_agg);
    cudaGetSymbolAddress((void**)&pH1, g_h1);
    cudaGetSymbolAddress((void**)&pH2, g_h2);

    cudaFuncSetAttribute(edge_mma_kernel,
                         cudaFuncAttributeMaxDynamicSharedMemorySize, EDGE_SMEM);

    // Prep: transpose (+zeroing) + projections + receiver sort
    transpose_w2_h<<<dim3(H_N / 32, M_N / 32, 2), dim3(32, 8)>>>(W2);
    layer1_gemm_h<<<dim3(H_N / 64, C_N / 32, 4), 256>>>(inputs, W1, b1);
    hist_kernel<<<128, 512>>>(rec_idx);
    scan_kernel<<<1, 512>>>();
    mkperm_kernel<<<256, 256>>>(rec_idx);

    // Main edge GEMM: persistent CTAs, B resident per class, dynamic tiles
    edge_mma_kernel<<<dim3(152, 4), 512, EDGE_SMEM>>>(
        b2, rel, send_idx, rec_idx);

    // Output MLP (fp32, 32x64 tiles -> full-SM parallelism)
    gemm32<<<dim3(OH_N / 64, C_N / 32), 256>>>(pAgg, Wo1, bo1, pH1, M_N, OH_N, 1);
    gemm32<<<dim3(OH_N / 64, C_N / 32), 256>>>(pH1, Wo2, bo2, pH2, OH_N, OH_N, 1);
    gemm32<<<dim3(D_N / 64, C_N / 32), 256>>>(pH2, Wo3, bo3, out, OH_N, D_N, 0);
}

// round 16
// speedup vs baseline: 1.2268x; 1.0248x over previous
#include <cuda_runtime.h>
#include <cuda_fp16.h>
#include <cstdint>

#define C_N 512
#define D_N 256
#define H_N 512
#define M_N 256
#define OH_N 512
#define E_N 261632

// ---------------------------------------------------------------------------
// Device scratch
// ---------------------------------------------------------------------------
__device__ __align__(16) __half g_Ph[4 * C_N * H_N];    // layer-1 projections, fp16
__device__ __align__(16) __half g_W2TH[2 * M_N * H_N];  // W2 transposed [t][n][k], fp16
__device__ __align__(16) float  g_agg[C_N * M_N];
__device__ __align__(16) float  g_h1[C_N * OH_N];
__device__ __align__(16) float  g_h2[C_N * OH_N];
__device__ int g_hist[512];
__device__ int g_cursor[512];
__device__ int g_perm[E_N];
__device__ int g_tileCtr[4];

// ---------------------------------------------------------------------------
// Helpers
// ---------------------------------------------------------------------------
__device__ __forceinline__ uint32_t smem_u32(const void* p) {
    uint32_t a;
    asm("{ .reg .u64 t; cvta.to.shared.u64 t, %1; cvt.u32.u64 %0, t; }" : "=r"(a) : "l"(p));
    return a;
}
__device__ __forceinline__ void cp16(uint32_t dst, const void* src) {
    asm volatile("cp.async.cg.shared.global [%0], [%1], 16;" :: "r"(dst), "l"(src));
}
#define CP_COMMIT() asm volatile("cp.async.commit_group;" ::: "memory")
#define CP_WAIT0()  asm volatile("cp.async.wait_group 0;" ::: "memory")

__device__ __forceinline__ void mma_f16(float* c, const uint32_t* a, const uint32_t* b) {
    asm volatile(
        "mma.sync.aligned.m16n8k16.row.col.f32.f16.f16.f32 "
        "{%0,%1,%2,%3}, {%4,%5,%6,%7}, {%8,%9}, {%0,%1,%2,%3};"
        : "+f"(c[0]), "+f"(c[1]), "+f"(c[2]), "+f"(c[3])
        : "r"(a[0]), "r"(a[1]), "r"(a[2]), "r"(a[3]), "r"(b[0]), "r"(b[1]));
}
__device__ __forceinline__ void ldmx4(uint32_t* r, uint32_t addr) {
    asm volatile("ldmatrix.sync.aligned.m8n8.x4.shared.b16 {%0,%1,%2,%3}, [%4];"
                 : "=r"(r[0]), "=r"(r[1]), "=r"(r[2]), "=r"(r[3]) : "r"(addr));
}

// ---------------------------------------------------------------------------
// fp32 GEMM, 32x64 tile, BK=32, 256 thr (proven R14)
// ---------------------------------------------------------------------------
__device__ __forceinline__ void gemm32_body(const float* __restrict__ A,
                                            const float* __restrict__ B,
                                            const float* __restrict__ bias,
                                            float* __restrict__ Cf,
                                            __half* __restrict__ Ch,
                                            int K, int N, int doRelu, int m0, int n0)
{
    __shared__ __align__(16) float sA[32][36];
    __shared__ __align__(16) float sB[32][68];

    int tid = threadIdx.x;
    int tx = tid & 15, ty = tid >> 4;
    float acc[2][4] = {};

    for (int k0 = 0; k0 < K; k0 += 32) {
        {
            int row = tid >> 3, cs = (tid & 7) * 4;
            float4 v = *(const float4*)(A + (size_t)(m0 + row) * K + k0 + cs);
            *(float4*)&sA[row][cs] = v;
        }
        {
            int kk = tid >> 3, cs = (tid & 7) * 8;
            const float* src = B + (size_t)(k0 + kk) * N + n0 + cs;
            float4 v0 = *(const float4*)(src);
            float4 v1 = *(const float4*)(src + 4);
            *(float4*)&sB[kk][cs]     = v0;
            *(float4*)&sB[kk][cs + 4] = v1;
        }
        __syncthreads();
        #pragma unroll
        for (int k = 0; k < 32; k++) {
            float a0 = sA[ty * 2][k];
            float a1 = sA[ty * 2 + 1][k];
            float4 bv = *(const float4*)&sB[k][tx * 4];
            acc[0][0] = fmaf(a0, bv.x, acc[0][0]);
            acc[0][1] = fmaf(a0, bv.y, acc[0][1]);
            acc[0][2] = fmaf(a0, bv.z, acc[0][2]);
            acc[0][3] = fmaf(a0, bv.w, acc[0][3]);
            acc[1][0] = fmaf(a1, bv.x, acc[1][0]);
            acc[1][1] = fmaf(a1, bv.y, acc[1][1]);
            acc[1][2] = fmaf(a1, bv.z, acc[1][2]);
            acc[1][3] = fmaf(a1, bv.w, acc[1][3]);
        }
        __syncthreads();
    }

    #pragma unroll
    for (int i = 0; i < 2; i++) {
        #pragma unroll
        for (int j = 0; j < 4; j++) {
            int n = n0 + tx * 4 + j;
            float v = acc[i][j] + (bias ? bias[n] : 0.0f);
            if (doRelu) v = fmaxf(v, 0.0f);
            if (Cf) Cf[(size_t)(m0 + ty * 2 + i) * N + n] = v;
            else    Ch[(size_t)(m0 + ty * 2 + i) * N + n] = __float2half_rn(v);
        }
    }
}

__global__ __launch_bounds__(256, 6)
void gemm32(const float* __restrict__ A, const float* __restrict__ B,
            const float* __restrict__ bias, float* __restrict__ Cmat,
            int K, int N, int doRelu)
{
    gemm32_body(A, B, bias, Cmat, nullptr, K, N, doRelu, blockIdx.y * 32, blockIdx.x * 64);
}

__global__ __launch_bounds__(256, 6)
void layer1_gemm_h(const float* __restrict__ inputs, const float* __restrict__ W1,
                   const float* __restrict__ b1)
{
    int z = blockIdx.z;
    const float* B = W1 + (size_t)z * D_N * H_N;
    const float* bias = ((z & 1) == 0) ? (b1 + (size_t)(z >> 1) * H_N) : nullptr;
    __half* outp = g_Ph + (size_t)z * C_N * H_N;
    gemm32_body(inputs, B, bias, nullptr, outp, D_N, H_N, 0,
                blockIdx.y * 32, blockIdx.x * 64);
}

// W2 transpose (+ folded zeroing of agg/hist/tileCtr)
__global__ void transpose_w2_h(const float* __restrict__ W2)
{
    __shared__ float tile[32][33];
    int t = blockIdx.z, k0 = blockIdx.x * 32, n0 = blockIdx.y * 32;
    const float* src = W2 + (size_t)t * H_N * M_N;
    __half* dst = g_W2TH + (size_t)t * M_N * H_N;
    int tid = threadIdx.y * 32 + threadIdx.x;

    {
        int bid = (blockIdx.z * gridDim.y + blockIdx.y) * gridDim.x + blockIdx.x;
        int gid = bid * 256 + tid;
        for (int i = gid; i < C_N * M_N; i += 65536) g_agg[i] = 0.0f;
        if (gid < 512) g_hist[gid] = 0;
        if (gid < 4)   g_tileCtr[gid] = 0;
    }

    #pragma unroll
    for (int i = 0; i < 4; i++)
        tile[threadIdx.y + i * 8][threadIdx.x] =
            src[(size_t)(k0 + threadIdx.y + i * 8) * M_N + n0 + threadIdx.x];
    __syncthreads();
    #pragma unroll
    for (int i = 0; i < 4; i++)
        dst[(size_t)(n0 + threadIdx.y + i * 8) * H_N + k0 + threadIdx.x] =
            __float2half_rn(tile[threadIdx.x][threadIdx.y + i * 8]);
}

// ---------------------------------------------------------------------------
// Counting sort of edges by receiver (proven R7/R11/R13)
// ---------------------------------------------------------------------------
__global__ __launch_bounds__(512)
void hist_kernel(const int* __restrict__ rec)
{
    __shared__ int h[512];
    int tid = threadIdx.x;
    h[tid] = 0;
    __syncthreads();
    for (int e = blockIdx.x * 512 + tid; e < E_N; e += gridDim.x * 512)
        atomicAdd(&h[rec[e]], 1);
    __syncthreads();
    atomicAdd(&g_hist[tid], h[tid]);
}

__global__ __launch_bounds__(512)
void scan_kernel()
{
    __shared__ int tmp[2][512];
    int tid = threadIdx.x;
    int v = g_hist[tid];
    tmp[0][tid] = v;
    __syncthreads();
    int src = 0;
    for (int off = 1; off < 512; off <<= 1) {
        int val = tmp[src][tid];
        if (tid >= off) val += tmp[src][tid - off];
        tmp[src ^ 1][tid] = val;
        src ^= 1;
        __syncthreads();
    }
    g_cursor[tid] = tmp[src][tid] - v;   // exclusive prefix
}

__global__ __launch_bounds__(256)
void mkperm_kernel(const int* __restrict__ rec)
{
    for (int e = blockIdx.x * blockDim.x + threadIdx.x; e < E_N;
         e += gridDim.x * blockDim.x) {
        int c = rec[e];
        int pos = atomicAdd(&g_cursor[c], 1);
        g_perm[pos] = e;
    }
}

// ---------------------------------------------------------------------------
// Edge kernel v11: persistent CTAs (R13/R14), KC=64 (8 barriers/tile).
// A staging FIXED: 2 threads/edge x 32 halves, prefetched in two 16-half
// waves (LDG_H0 -> ks0,1 -> STORE_H0 + LDG_H1 -> ks2,3 -> STORE_H1 -> sync).
// ROWA=72 conflict-free. B resident, dynamic tiles, shfl-reduced scatter.
// ---------------------------------------------------------------------------
#define ET 256
#define ROWA 72
#define ROWB 520
#define A_STAGE_H (ET * ROWA)        // 18432 halves (36KB)
#define B_FULL_H  (128 * ROWB)       // 66560 halves (133KB)
#define NKC (H_N / 64)               // 8
#define NTILES (E_N / ET)            // 1022
#define EDGE_SMEM ((B_FULL_H + 2 * A_STAGE_H) * 2)   // 206848 B

__global__ __launch_bounds__(512, 1)
void edge_mma_kernel(const float* __restrict__ b2, const float* __restrict__ rel,
                     const int* __restrict__ send, const int* __restrict__ rec)
{
    extern __shared__ __align__(16) __half dsm[];
    __half* sBfull = dsm;                      // [128][ROWB] resident
    __half* sAbuf  = dsm + B_FULL_H;           // 2 stages [ET][ROWA]
    __shared__ float s_relt[ET];
    __shared__ int   s_r[ET];
    __shared__ int   s_p[ET];
    __shared__ float s_b2[128];
    __shared__ int   s_tile;

    const int tid  = threadIdx.x;
    const int lane = tid & 31;
    const int warp = tid >> 5;
    const int mb  = (warp & 3) * 64;      // 64-edge strip
    const int nbw = (warp >> 2) * 32;     // 32-col strip
    const int cls = blockIdx.y;           // 0..3
    const int t   = cls >> 1;
    const int n0  = (cls & 1) * 128;
    const int r4 = lane >> 2, c4 = lane & 3;

    const uint32_t sB_u32 = smem_u32(sBfull);
    const uint32_t sA_u32 = smem_u32(sAbuf);

    // ---- B resident load (once per CTA) ----
    {
        const int row = tid >> 2;
        const int bq = tid & 3;
        const __half* src = g_W2TH + ((size_t)t * M_N + n0 + row) * H_N + bq * 128;
        uint32_t d = sB_u32 + (uint32_t)(row * ROWB + bq * 128) * 2u;
        #pragma unroll
        for (int j = 0; j < 16; j++)
            cp16(d + j * 16, src + j * 8);
        CP_COMMIT();
    }
    if (tid < 128) s_b2[tid] = b2[t * M_N + n0 + tid];

    // ldmatrix per-lane base addresses (bytes)
    const int lrA = lane & 15;
    const int khA = (lane >> 4) * 8;
    const int lrB = ((lane >> 4) & 1) * 8 + (lane & 7);
    const int khB = ((lane >> 3) & 1) * 8;
    uint32_t aBase[4], bBase[2];
    #pragma unroll
    for (int mt = 0; mt < 4; mt++)
        aBase[mt] = sA_u32 + (uint32_t)((mb + mt * 16 + lrA) * ROWA + khA) * 2u;
    #pragma unroll
    for (int p = 0; p < 2; p++)
        bBase[p] = sB_u32 + (uint32_t)((nbw + p * 16 + lrB) * ROWB + khB) * 2u;

    // A staging: 2 threads per edge, halves [lq*32, lq*32+32) of each chunk
    const int le = tid >> 1;   // 0..255
    const int lq = tid & 1;
    const __half2 zero2 = __float2half2_rn(0.0f);

    CP_WAIT0();   // B resident complete (sealed by first barrier)

    // ---- persistent tile loop ----
    for (;;) {
        if (tid == 0) s_tile = atomicAdd(&g_tileCtr[cls], 1);
        __syncthreads();
        const int tile = s_tile;
        if (tile >= NTILES) break;
        const int e0 = tile * ET;

        if (tid < ET) {
            int p = g_perm[e0 + tid];
            s_p[tid] = p;
            s_r[tid] = rec[p];
            s_relt[tid] = rel[(size_t)p * 2 + t];
        }
        __syncthreads();

        const int sn = send[s_p[le]];
        const int rn = s_r[le];
        const __half* PS = g_Ph + ((size_t)(t * 2 + 0) * C_N + sn) * H_N + lq * 32;
        const __half* PR = g_Ph + ((size_t)(t * 2 + 1) * C_N + rn) * H_N + lq * 32;

        float acc[4][4][4];
        #pragma unroll
        for (int i = 0; i < 4; i++)
            #pragma unroll
            for (int j = 0; j < 4; j++)
                #pragma unroll
                for (int q = 0; q < 4; q++) acc[i][j][q] = 0.0f;

        uint4 pa0, pa1, pb0, pb1;

// Load 16 halves (of this thread's 32-half window) from each of PS/PR.
// hoff = 0 or 16 within the window; chunk offset = kchunk*64 halves.
#define A_LDG16(kchunk, hoff)                                                 \
    do {                                                                      \
        const __half* ps = PS + (kchunk) * 64 + (hoff);                       \
        const __half* pr = PR + (kchunk) * 64 + (hoff);                       \
        pa0 = *(const uint4*)ps;       pa1 = *(const uint4*)(ps + 8);         \
        pb0 = *(const uint4*)pr;       pb1 = *(const uint4*)(pr + 8);         \
    } while (0)

// Combine relu(PS+PR) and store 16 halves at the matching offset.
#define A_STORE16(stOff, hoff)                                                \
    do {                                                                      \
        __half2 hh[8];                                                        \
        const __half2* xa0 = (const __half2*)&pa0;                            \
        const __half2* xa1 = (const __half2*)&pa1;                            \
        const __half2* xb0 = (const __half2*)&pb0;                            \
        const __half2* xb1 = (const __half2*)&pb1;                            \
        _Pragma("unroll")                                                     \
        for (int i = 0; i < 4; i++) {                                         \
            hh[i]     = __hmax2(__hadd2(xa0[i], xb0[i]), zero2);              \
            hh[i + 4] = __hmax2(__hadd2(xa1[i], xb1[i]), zero2);              \
        }                                                                     \
        __half* dstA = sAbuf + (stOff) + le * ROWA + lq * 32 + (hoff);        \
        *(uint4*)dstA       = *(uint4*)&hh[0];                                \
        *(uint4*)(dstA + 8) = *(uint4*)&hh[4];                                \
    } while (0)

        // ---- A prologue: full chunk0 -> stage0 ----
        A_LDG16(0, 0);
        A_STORE16(0, 0);
        A_LDG16(0, 16);
        A_STORE16(0, 16);
        __syncthreads();

        #pragma unroll 1
        for (int kc = 0; kc < NKC; kc++) {
            const int cur = kc & 1;
            const uint32_t nxtOff = (uint32_t)((cur ^ 1) * A_STAGE_H);
            const bool more = (kc + 1 < NKC);
            if (more) A_LDG16(kc + 1, 0);   // prefetch half0 of next chunk

            const uint32_t aOff = (uint32_t)(cur * A_STAGE_H) * 2u;
            const uint32_t bK = (uint32_t)(kc * 128);   // bytes (kc*64 halves)

            // ---- MMA ks 0,1 ----
            #pragma unroll
            for (int ks = 0; ks < 2; ks++) {
                uint32_t af[4][4];
                #pragma unroll
                for (int mt = 0; mt < 4; mt++)
                    ldmx4(af[mt], aBase[mt] + aOff + ks * 32);
                uint32_t bf[4][2];
                {
                    uint32_t r[4];
                    ldmx4(r, bBase[0] + bK + ks * 32);
                    bf[0][0] = r[0]; bf[0][1] = r[1]; bf[1][0] = r[2]; bf[1][1] = r[3];
                    ldmx4(r, bBase[1] + bK + ks * 32);
                    bf[2][0] = r[0]; bf[2][1] = r[1]; bf[3][0] = r[2]; bf[3][1] = r[3];
                }
                #pragma unroll
                for (int nt = 0; nt < 4; nt++)
                    #pragma unroll
                    for (int mt = 0; mt < 4; mt++)
                        mma_f16(acc[mt][nt], af[mt], bf[nt]);
            }

            if (more) {
                A_STORE16(nxtOff, 0);        // store half0
                A_LDG16(kc + 1, 16);         // prefetch half1
            }

            // ---- MMA ks 2,3 ----
            #pragma unroll
            for (int ks = 2; ks < 4; ks++) {
                uint32_t af[4][4];
                #pragma unroll
                for (int mt = 0; mt < 4; mt++)
                    ldmx4(af[mt], aBase[mt] + aOff + ks * 32);
                uint32_t bf[4][2];
                {
                    uint32_t r[4];
                    ldmx4(r, bBase[0] + bK + ks * 32);
                    bf[0][0] = r[0]; bf[0][1] = r[1]; bf[1][0] = r[2]; bf[1][1] = r[3];
                    ldmx4(r, bBase[1] + bK + ks * 32);
                    bf[2][0] = r[0]; bf[2][1] = r[1]; bf[3][0] = r[2]; bf[3][1] = r[3];
                }
                #pragma unroll
                for (int nt = 0; nt < 4; nt++)
                    #pragma unroll
                    for (int mt = 0; mt < 4; mt++)
                        mma_f16(acc[mt][nt], af[mt], bf[nt]);
            }

            if (more) A_STORE16(nxtOff, 16); // store half1
            __syncthreads();
        }
#undef A_LDG16
#undef A_STORE16

        // ---- epilogue: shfl-reduced scatter over sorted receivers ----
        const bool uniform = (s_r[mb] == s_r[mb + 63]);
        if (uniform) {
            float cs[4][2];
            #pragma unroll
            for (int nt = 0; nt < 4; nt++) { cs[nt][0] = 0.0f; cs[nt][1] = 0.0f; }
            #pragma unroll
            for (int mt = 0; mt < 4; mt++) {
                const int row0 = mb + mt * 16 + r4;
                const float w0 = s_relt[row0];
                const float w1 = s_relt[row0 + 8];
                #pragma unroll
                for (int nt = 0; nt < 4; nt++) {
                    const int col = nbw + nt * 8 + 2 * c4;
                    const float bb0 = s_b2[col];
                    const float bb1 = s_b2[col + 1];
                    cs[nt][0] += w0 * fmaxf(acc[mt][nt][0] + bb0, 0.0f)
                               + w1 * fmaxf(acc[mt][nt][2] + bb0, 0.0f);
                    cs[nt][1] += w0 * fmaxf(acc[mt][nt][1] + bb1, 0.0f)
                               + w1 * fmaxf(acc[mt][nt][3] + bb1, 0.0f);
                }
            }
            #pragma unroll
            for (int off = 4; off < 32; off <<= 1)
                #pragma unroll
                for (int nt = 0; nt < 4; nt++) {
                    cs[nt][0] += __shfl_xor_sync(0xFFFFFFFFu, cs[nt][0], off);
                    cs[nt][1] += __shfl_xor_sync(0xFFFFFFFFu, cs[nt][1], off);
                }
            if (lane < 4) {
                float* dst = g_agg + (size_t)s_r[mb] * M_N + n0;
                #pragma unroll
                for (int nt = 0; nt < 4; nt++) {
                    const int col = nbw + nt * 8 + 2 * c4;
                    atomicAdd(dst + col,     cs[nt][0]);
                    atomicAdd(dst + col + 1, cs[nt][1]);
                }
            }
        } else {
            #pragma unroll
            for (int mt = 0; mt < 4; mt++) {
                const int row0 = mb + mt * 16 + r4;
                const int row1 = row0 + 8;
                const float w0 = s_relt[row0];
                const float w1 = s_relt[row1];
                float* d0 = g_agg + (size_t)s_r[row0] * M_N + n0;
                float* d1 = g_agg + (size_t)s_r[row1] * M_N + n0;
                #pragma unroll
                for (int nt = 0; nt < 4; nt++) {
                    const int col = nbw + nt * 8 + 2 * c4;
                    const float bb0 = s_b2[col];
                    const float bb1 = s_b2[col + 1];
                    atomicAdd(d0 + col,     w0 * fmaxf(acc[mt][nt][0] + bb0, 0.0f));
                    atomicAdd(d0 + col + 1, w0 * fmaxf(acc[mt][nt][1] + bb1, 0.0f));
                    atomicAdd(d1 + col,     w1 * fmaxf(acc[mt][nt][2] + bb0, 0.0f));
                    atomicAdd(d1 + col + 1, w1 * fmaxf(acc[mt][nt][3] + bb1, 0.0f));
                }
            }
        }
    }
}

// ---------------------------------------------------------------------------
// Launch
// ---------------------------------------------------------------------------
extern "C" void kernel_launch(void* const* d_in, const int* in_sizes, int n_in,
                              void* d_out, int out_size)
{
    const float* inputs = (const float*)d_in[0];
    const float* rel    = (const float*)d_in[1];
    const float* W1     = (const float*)d_in[2];
    const float* b1     = (const float*)d_in[3];
    const float* W2     = (const float*)d_in[4];
    const float* b2     = (const float*)d_in[5];
    const float* Wo1    = (const float*)d_in[6];
    const float* bo1    = (const float*)d_in[7];
    const float* Wo2    = (const float*)d_in[8];
    const float* bo2    = (const float*)d_in[9];
    const float* Wo3    = (const float*)d_in[10];
    const float* bo3    = (const float*)d_in[11];
    const int* send_idx = (const int*)d_in[12];
    const int* rec_idx  = (const int*)d_in[13];
    float* out = (float*)d_out;

    float *pAgg, *pH1, *pH2;
    cudaGetSymbolAddress((void**)&pAgg, g_agg);
    cudaGetSymbolAddress((void**)&pH1, g_h1);
    cudaGetSymbolAddress((void**)&pH2, g_h2);

    cudaFuncSetAttribute(edge_mma_kernel,
                         cudaFuncAttributeMaxDynamicSharedMemorySize, EDGE_SMEM);

    // Prep: transpose (+zeroing) + projections + receiver sort
    transpose_w2_h<<<dim3(H_N / 32, M_N / 32, 2), dim3(32, 8)>>>(W2);
    layer1_gemm_h<<<dim3(H_N / 64, C_N / 32, 4), 256>>>(inputs, W1, b1);
    hist_kernel<<<128, 512>>>(rec_idx);
    scan_kernel<<<1, 512>>>();
    mkperm_kernel<<<256, 256>>>(rec_idx);

    // Main edge GEMM: persistent CTAs, B resident, KC=64, dynamic tiles
    edge_mma_kernel<<<dim3(152, 4), 512, EDGE_SMEM>>>(
        b2, rel, send_idx, rec_idx);

    // Output MLP (fp32, 32x64 tiles)
    gemm32<<<dim3(OH_N / 64, C_N / 32), 256>>>(pAgg, Wo1, bo1, pH1, M_N, OH_N, 1);
    gemm32<<<dim3(OH_N / 64, C_N / 32), 256>>>(pH1, Wo2, bo2, pH2, OH_N, OH_N, 1);
    gemm32<<<dim3(D_N / 64, C_N / 32), 256>>>(pH2, Wo3, bo3, out, OH_N, D_N, 0);
}

// round 17
// speedup vs baseline: 1.2758x; 1.0400x over previous
#include <cuda_runtime.h>
#include <cuda_fp16.h>
#include <cstdint>

#define C_N 512
#define D_N 256
#define H_N 512
#define M_N 256
#define OH_N 512
#define E_N 261632

// ---------------------------------------------------------------------------
// Device scratch
// ---------------------------------------------------------------------------
__device__ __align__(16) __half g_Ph[4 * C_N * H_N];
__device__ __align__(16) __half g_W2TH[2 * M_N * H_N];
__device__ __align__(16) float  g_agg[C_N * M_N];
__device__ __align__(16) float  g_h1[C_N * OH_N];
__device__ __align__(16) float  g_h2[C_N * OH_N];
__device__ int g_hist[512];
__device__ int g_cursor[512];
__device__ int g_perm[E_N];
__device__ int g_tileCtr[4];

// ---------------------------------------------------------------------------
// Helpers
// ---------------------------------------------------------------------------
__device__ __forceinline__ uint32_t smem_u32(const void* p) {
    uint32_t a;
    asm("{ .reg .u64 t; cvta.to.shared.u64 t, %1; cvt.u32.u64 %0, t; }" : "=r"(a) : "l"(p));
    return a;
}
__device__ __forceinline__ void cp16(uint32_t dst, const void* src) {
    asm volatile("cp.async.cg.shared.global [%0], [%1], 16;" :: "r"(dst), "l"(src));
}
#define CP_COMMIT() asm volatile("cp.async.commit_group;" ::: "memory")
#define CP_WAIT0()  asm volatile("cp.async.wait_group 0;" ::: "memory")

__device__ __forceinline__ void mma_f16(float* c, const uint32_t* a, const uint32_t* b) {
    asm volatile(
        "mma.sync.aligned.m16n8k16.row.col.f32.f16.f16.f32 "
        "{%0,%1,%2,%3}, {%4,%5,%6,%7}, {%8,%9}, {%0,%1,%2,%3};"
        : "+f"(c[0]), "+f"(c[1]), "+f"(c[2]), "+f"(c[3])
        : "r"(a[0]), "r"(a[1]), "r"(a[2]), "r"(a[3]), "r"(b[0]), "r"(b[1]));
}
__device__ __forceinline__ void ldmx4(uint32_t* r, uint32_t addr) {
    asm volatile("ldmatrix.sync.aligned.m8n8.x4.shared.b16 {%0,%1,%2,%3}, [%4];"
                 : "=r"(r[0]), "=r"(r[1]), "=r"(r[2]), "=r"(r[3]) : "r"(addr));
}

// ---------------------------------------------------------------------------
// fp32 GEMM, 32x64 tile, BK=32, 256 thr (proven R14/R16)
// ---------------------------------------------------------------------------
__device__ __forceinline__ void gemm32_body(const float* __restrict__ A,
                                            const float* __restrict__ B,
                                            const float* __restrict__ bias,
                                            float* __restrict__ Cf,
                                            __half* __restrict__ Ch,
                                            int K, int N, int doRelu, int m0, int n0)
{
    __shared__ __align__(16) float sA[32][36];
    __shared__ __align__(16) float sB[32][68];

    int tid = threadIdx.x;
    int tx = tid & 15, ty = tid >> 4;
    float acc[2][4] = {};

    for (int k0 = 0; k0 < K; k0 += 32) {
        {
            int row = tid >> 3, cs = (tid & 7) * 4;
            float4 v = *(const float4*)(A + (size_t)(m0 + row) * K + k0 + cs);
            *(float4*)&sA[row][cs] = v;
        }
        {
            int kk = tid >> 3, cs = (tid & 7) * 8;
            const float* src = B + (size_t)(k0 + kk) * N + n0 + cs;
            float4 v0 = *(const float4*)(src);
            float4 v1 = *(const float4*)(src + 4);
            *(float4*)&sB[kk][cs]     = v0;
            *(float4*)&sB[kk][cs + 4] = v1;
        }
        __syncthreads();
        #pragma unroll
        for (int k = 0; k < 32; k++) {
            float a0 = sA[ty * 2][k];
            float a1 = sA[ty * 2 + 1][k];
            float4 bv = *(const float4*)&sB[k][tx * 4];
            acc[0][0] = fmaf(a0, bv.x, acc[0][0]);
            acc[0][1] = fmaf(a0, bv.y, acc[0][1]);
            acc[0][2] = fmaf(a0, bv.z, acc[0][2]);
            acc[0][3] = fmaf(a0, bv.w, acc[0][3]);
            acc[1][0] = fmaf(a1, bv.x, acc[1][0]);
            acc[1][1] = fmaf(a1, bv.y, acc[1][1]);
            acc[1][2] = fmaf(a1, bv.z, acc[1][2]);
            acc[1][3] = fmaf(a1, bv.w, acc[1][3]);
        }
        __syncthreads();
    }

    #pragma unroll
    for (int i = 0; i < 2; i++) {
        #pragma unroll
        for (int j = 0; j < 4; j++) {
            int n = n0 + tx * 4 + j;
            float v = acc[i][j] + (bias ? bias[n] : 0.0f);
            if (doRelu) v = fmaxf(v, 0.0f);
            if (Cf) Cf[(size_t)(m0 + ty * 2 + i) * N + n] = v;
            else    Ch[(size_t)(m0 + ty * 2 + i) * N + n] = __float2half_rn(v);
        }
    }
}

__global__ __launch_bounds__(256, 6)
void gemm32(const float* __restrict__ A, const float* __restrict__ B,
            const float* __restrict__ bias, float* __restrict__ Cmat,
            int K, int N, int doRelu)
{
    gemm32_body(A, B, bias, Cmat, nullptr, K, N, doRelu, blockIdx.y * 32, blockIdx.x * 64);
}

__global__ __launch_bounds__(256, 6)
void layer1_gemm_h(const float* __restrict__ inputs, const float* __restrict__ W1,
                   const float* __restrict__ b1)
{
    int z = blockIdx.z;
    const float* B = W1 + (size_t)z * D_N * H_N;
    const float* bias = ((z & 1) == 0) ? (b1 + (size_t)(z >> 1) * H_N) : nullptr;
    __half* outp = g_Ph + (size_t)z * C_N * H_N;
    gemm32_body(inputs, B, bias, nullptr, outp, D_N, H_N, 0,
                blockIdx.y * 32, blockIdx.x * 64);
}

// W2 transpose (+ folded zeroing of agg/hist/tileCtr)
__global__ void transpose_w2_h(const float* __restrict__ W2)
{
    __shared__ float tile[32][33];
    int t = blockIdx.z, k0 = blockIdx.x * 32, n0 = blockIdx.y * 32;
    const float* src = W2 + (size_t)t * H_N * M_N;
    __half* dst = g_W2TH + (size_t)t * M_N * H_N;
    int tid = threadIdx.y * 32 + threadIdx.x;

    {
        int bid = (blockIdx.z * gridDim.y + blockIdx.y) * gridDim.x + blockIdx.x;
        int gid = bid * 256 + tid;
        for (int i = gid; i < C_N * M_N; i += 65536) g_agg[i] = 0.0f;
        if (gid < 512) g_hist[gid] = 0;
        if (gid < 4)   g_tileCtr[gid] = 0;
    }

    #pragma unroll
    for (int i = 0; i < 4; i++)
        tile[threadIdx.y + i * 8][threadIdx.x] =
            src[(size_t)(k0 + threadIdx.y + i * 8) * M_N + n0 + threadIdx.x];
    __syncthreads();
    #pragma unroll
    for (int i = 0; i < 4; i++)
        dst[(size_t)(n0 + threadIdx.y + i * 8) * H_N + k0 + threadIdx.x] =
            __float2half_rn(tile[threadIdx.x][threadIdx.y + i * 8]);
}

// ---------------------------------------------------------------------------
// Counting sort of edges by receiver (proven)
// ---------------------------------------------------------------------------
__global__ __launch_bounds__(512)
void hist_kernel(const int* __restrict__ rec)
{
    __shared__ int h[512];
    int tid = threadIdx.x;
    h[tid] = 0;
    __syncthreads();
    for (int e = blockIdx.x * 512 + tid; e < E_N; e += gridDim.x * 512)
        atomicAdd(&h[rec[e]], 1);
    __syncthreads();
    atomicAdd(&g_hist[tid], h[tid]);
}

__global__ __launch_bounds__(512)
void scan_kernel()
{
    __shared__ int tmp[2][512];
    int tid = threadIdx.x;
    int v = g_hist[tid];
    tmp[0][tid] = v;
    __syncthreads();
    int src = 0;
    for (int off = 1; off < 512; off <<= 1) {
        int val = tmp[src][tid];
        if (tid >= off) val += tmp[src][tid - off];
        tmp[src ^ 1][tid] = val;
        src ^= 1;
        __syncthreads();
    }
    g_cursor[tid] = tmp[src][tid] - v;
}

__global__ __launch_bounds__(256)
void mkperm_kernel(const int* __restrict__ rec)
{
    for (int e = blockIdx.x * blockDim.x + threadIdx.x; e < E_N;
         e += gridDim.x * blockDim.x) {
        int c = rec[e];
        int pos = atomicAdd(&g_cursor[c], 1);
        g_perm[pos] = e;
    }
}

// ---------------------------------------------------------------------------
// Edge kernel v12: R16 structure (persistent, B resident, KC=64) with a
// two-segment shfl-reduced epilogue for boundary strips (sorted s_r is
// non-decreasing; >2 receivers per 64-row strip falls back to per-row).
// ---------------------------------------------------------------------------
#define ET 256
#define ROWA 72
#define ROWB 520
#define A_STAGE_H (ET * ROWA)
#define B_FULL_H  (128 * ROWB)
#define NKC (H_N / 64)
#define NTILES (E_N / ET)
#define EDGE_SMEM ((B_FULL_H + 2 * A_STAGE_H) * 2)   // 206848 B

__global__ __launch_bounds__(512, 1)
void edge_mma_kernel(const float* __restrict__ b2, const float* __restrict__ rel,
                     const int* __restrict__ send, const int* __restrict__ rec)
{
    extern __shared__ __align__(16) __half dsm[];
    __half* sBfull = dsm;
    __half* sAbuf  = dsm + B_FULL_H;
    __shared__ float s_relt[ET];
    __shared__ int   s_r[ET];
    __shared__ int   s_p[ET];
    __shared__ float s_b2[128];
    __shared__ int   s_tile;

    const int tid  = threadIdx.x;
    const int lane = tid & 31;
    const int warp = tid >> 5;
    const int mb  = (warp & 3) * 64;
    const int nbw = (warp >> 2) * 32;
    const int cls = blockIdx.y;
    const int t   = cls >> 1;
    const int n0  = (cls & 1) * 128;
    const int r4 = lane >> 2, c4 = lane & 3;

    const uint32_t sB_u32 = smem_u32(sBfull);
    const uint32_t sA_u32 = smem_u32(sAbuf);

    // ---- B resident load (once per CTA) ----
    {
        const int row = tid >> 2;
        const int bq = tid & 3;
        const __half* src = g_W2TH + ((size_t)t * M_N + n0 + row) * H_N + bq * 128;
        uint32_t d = sB_u32 + (uint32_t)(row * ROWB + bq * 128) * 2u;
        #pragma unroll
        for (int j = 0; j < 16; j++)
            cp16(d + j * 16, src + j * 8);
        CP_COMMIT();
    }
    if (tid < 128) s_b2[tid] = b2[t * M_N + n0 + tid];

    const int lrA = lane & 15;
    const int khA = (lane >> 4) * 8;
    const int lrB = ((lane >> 4) & 1) * 8 + (lane & 7);
    const int khB = ((lane >> 3) & 1) * 8;
    uint32_t aBase[4], bBase[2];
    #pragma unroll
    for (int mt = 0; mt < 4; mt++)
        aBase[mt] = sA_u32 + (uint32_t)((mb + mt * 16 + lrA) * ROWA + khA) * 2u;
    #pragma unroll
    for (int p = 0; p < 2; p++)
        bBase[p] = sB_u32 + (uint32_t)((nbw + p * 16 + lrB) * ROWB + khB) * 2u;

    const int le = tid >> 1;
    const int lq = tid & 1;
    const __half2 zero2 = __float2half2_rn(0.0f);

    CP_WAIT0();

    for (;;) {
        if (tid == 0) s_tile = atomicAdd(&g_tileCtr[cls], 1);
        __syncthreads();
        const int tile = s_tile;
        if (tile >= NTILES) break;
        const int e0 = tile * ET;

        if (tid < ET) {
            int p = g_perm[e0 + tid];
            s_p[tid] = p;
            s_r[tid] = rec[p];
            s_relt[tid] = rel[(size_t)p * 2 + t];
        }
        __syncthreads();

        const int sn = send[s_p[le]];
        const int rn = s_r[le];
        const __half* PS = g_Ph + ((size_t)(t * 2 + 0) * C_N + sn) * H_N + lq * 32;
        const __half* PR = g_Ph + ((size_t)(t * 2 + 1) * C_N + rn) * H_N + lq * 32;

        float acc[4][4][4];
        #pragma unroll
        for (int i = 0; i < 4; i++)
            #pragma unroll
            for (int j = 0; j < 4; j++)
                #pragma unroll
                for (int q = 0; q < 4; q++) acc[i][j][q] = 0.0f;

        uint4 pa0, pa1, pb0, pb1;

#define A_LDG16(kchunk, hoff)                                                 \
    do {                                                                      \
        const __half* ps = PS + (kchunk) * 64 + (hoff);                       \
        const __half* pr = PR + (kchunk) * 64 + (hoff);                       \
        pa0 = *(const uint4*)ps;       pa1 = *(const uint4*)(ps + 8);         \
        pb0 = *(const uint4*)pr;       pb1 = *(const uint4*)(pr + 8);         \
    } while (0)

#define A_STORE16(stOff, hoff)                                                \
    do {                                                                      \
        __half2 hh[8];                                                        \
        const __half2* xa0 = (const __half2*)&pa0;                            \
        const __half2* xa1 = (const __half2*)&pa1;                            \
        const __half2* xb0 = (const __half2*)&pb0;                            \
        const __half2* xb1 = (const __half2*)&pb1;                            \
        _Pragma("unroll")                                                     \
        for (int i = 0; i < 4; i++) {                                         \
            hh[i]     = __hmax2(__hadd2(xa0[i], xb0[i]), zero2);              \
            hh[i + 4] = __hmax2(__hadd2(xa1[i], xb1[i]), zero2);              \
        }                                                                     \
        __half* dstA = sAbuf + (stOff) + le * ROWA + lq * 32 + (hoff);        \
        *(uint4*)dstA       = *(uint4*)&hh[0];                                \
        *(uint4*)(dstA + 8) = *(uint4*)&hh[4];                                \
    } while (0)

        A_LDG16(0, 0);
        A_STORE16(0, 0);
        A_LDG16(0, 16);
        A_STORE16(0, 16);
        __syncthreads();

        #pragma unroll 1
        for (int kc = 0; kc < NKC; kc++) {
            const int cur = kc & 1;
            const uint32_t nxtOff = (uint32_t)((cur ^ 1) * A_STAGE_H);
            const bool more = (kc + 1 < NKC);
            if (more) A_LDG16(kc + 1, 0);

            const uint32_t aOff = (uint32_t)(cur * A_STAGE_H) * 2u;
            const uint32_t bK = (uint32_t)(kc * 128);

            #pragma unroll
            for (int ks = 0; ks < 2; ks++) {
                uint32_t af[4][4];
                #pragma unroll
                for (int mt = 0; mt < 4; mt++)
                    ldmx4(af[mt], aBase[mt] + aOff + ks * 32);
                uint32_t bf[4][2];
                {
                    uint32_t r[4];
                    ldmx4(r, bBase[0] + bK + ks * 32);
                    bf[0][0] = r[0]; bf[0][1] = r[1]; bf[1][0] = r[2]; bf[1][1] = r[3];
                    ldmx4(r, bBase[1] + bK + ks * 32);
                    bf[2][0] = r[0]; bf[2][1] = r[1]; bf[3][0] = r[2]; bf[3][1] = r[3];
                }
                #pragma unroll
                for (int nt = 0; nt < 4; nt++)
                    #pragma unroll
                    for (int mt = 0; mt < 4; mt++)
                        mma_f16(acc[mt][nt], af[mt], bf[nt]);
            }

            if (more) {
                A_STORE16(nxtOff, 0);
                A_LDG16(kc + 1, 16);
            }

            #pragma unroll
            for (int ks = 2; ks < 4; ks++) {
                uint32_t af[4][4];
                #pragma unroll
                for (int mt = 0; mt < 4; mt++)
                    ldmx4(af[mt], aBase[mt] + aOff + ks * 32);
                uint32_t bf[4][2];
                {
                    uint32_t r[4];
                    ldmx4(r, bBase[0] + bK + ks * 32);
                    bf[0][0] = r[0]; bf[0][1] = r[1]; bf[1][0] = r[2]; bf[1][1] = r[3];
                    ldmx4(r, bBase[1] + bK + ks * 32);
                    bf[2][0] = r[0]; bf[2][1] = r[1]; bf[3][0] = r[2]; bf[3][1] = r[3];
                }
                #pragma unroll
                for (int nt = 0; nt < 4; nt++)
                    #pragma unroll
                    for (int mt = 0; mt < 4; mt++)
                        mma_f16(acc[mt][nt], af[mt], bf[nt]);
            }

            if (more) A_STORE16(nxtOff, 16);
            __syncthreads();
        }
#undef A_LDG16
#undef A_STORE16

        // ---- epilogue: shfl-reduced scatter (1-seg / 2-seg / fallback) ----
        const int rA = s_r[mb];
        const int rB = s_r[mb + 63];

        // Check: do this thread's 8 rows all belong to {rA, rB}?
        bool only2 = true;
        #pragma unroll
        for (int mt = 0; mt < 4; mt++) {
            int rr0 = s_r[mb + mt * 16 + r4];
            int rr1 = s_r[mb + mt * 16 + r4 + 8];
            only2 &= (rr0 == rA || rr0 == rB);
            only2 &= (rr1 == rA || rr1 == rB);
        }
        only2 = __all_sync(0xFFFFFFFFu, only2);

        if (rA == rB) {
            // single receiver: one reduction
            float cs[4][2];
            #pragma unroll
            for (int nt = 0; nt < 4; nt++) { cs[nt][0] = 0.0f; cs[nt][1] = 0.0f; }
            #pragma unroll
            for (int mt = 0; mt < 4; mt++) {
                const int row0 = mb + mt * 16 + r4;
                const float w0 = s_relt[row0];
                const float w1 = s_relt[row0 + 8];
                #pragma unroll
                for (int nt = 0; nt < 4; nt++) {
                    const int col = nbw + nt * 8 + 2 * c4;
                    const float bb0 = s_b2[col];
                    const float bb1 = s_b2[col + 1];
                    cs[nt][0] += w0 * fmaxf(acc[mt][nt][0] + bb0, 0.0f)
                               + w1 * fmaxf(acc[mt][nt][2] + bb0, 0.0f);
                    cs[nt][1] += w0 * fmaxf(acc[mt][nt][1] + bb1, 0.0f)
                               + w1 * fmaxf(acc[mt][nt][3] + bb1, 0.0f);
                }
            }
            #pragma unroll
            for (int off = 4; off < 32; off <<= 1)
                #pragma unroll
                for (int nt = 0; nt < 4; nt++) {
                    cs[nt][0] += __shfl_xor_sync(0xFFFFFFFFu, cs[nt][0], off);
                    cs[nt][1] += __shfl_xor_sync(0xFFFFFFFFu, cs[nt][1], off);
                }
            if (lane < 4) {
                float* dst = g_agg + (size_t)rA * M_N + n0;
                #pragma unroll
                for (int nt = 0; nt < 4; nt++) {
                    const int col = nbw + nt * 8 + 2 * c4;
                    atomicAdd(dst + col,     cs[nt][0]);
                    atomicAdd(dst + col + 1, cs[nt][1]);
                }
            }
        } else if (only2) {
            // two receivers: split contributions, two reductions
            float ca[4][2], cb[4][2];
            #pragma unroll
            for (int nt = 0; nt < 4; nt++) {
                ca[nt][0] = 0.0f; ca[nt][1] = 0.0f;
                cb[nt][0] = 0.0f; cb[nt][1] = 0.0f;
            }
            #pragma unroll
            for (int mt = 0; mt < 4; mt++) {
                const int row0 = mb + mt * 16 + r4;
                const int row1 = row0 + 8;
                const float w0 = s_relt[row0];
                const float w1 = s_relt[row1];
                const bool a0 = (s_r[row0] == rA);
                const bool a1 = (s_r[row1] == rA);
                #pragma unroll
                for (int nt = 0; nt < 4; nt++) {
                    const int col = nbw + nt * 8 + 2 * c4;
                    const float bb0 = s_b2[col];
                    const float bb1 = s_b2[col + 1];
                    float v00 = w0 * fmaxf(acc[mt][nt][0] + bb0, 0.0f);
                    float v01 = w0 * fmaxf(acc[mt][nt][1] + bb1, 0.0f);
                    float v10 = w1 * fmaxf(acc[mt][nt][2] + bb0, 0.0f);
                    float v11 = w1 * fmaxf(acc[mt][nt][3] + bb1, 0.0f);
                    if (a0) { ca[nt][0] += v00; ca[nt][1] += v01; }
                    else    { cb[nt][0] += v00; cb[nt][1] += v01; }
                    if (a1) { ca[nt][0] += v10; ca[nt][1] += v11; }
                    else    { cb[nt][0] += v10; cb[nt][1] += v11; }
                }
            }
            #pragma unroll
            for (int off = 4; off < 32; off <<= 1)
                #pragma unroll
                for (int nt = 0; nt < 4; nt++) {
                    ca[nt][0] += __shfl_xor_sync(0xFFFFFFFFu, ca[nt][0], off);
                    ca[nt][1] += __shfl_xor_sync(0xFFFFFFFFu, ca[nt][1], off);
                    cb[nt][0] += __shfl_xor_sync(0xFFFFFFFFu, cb[nt][0], off);
                    cb[nt][1] += __shfl_xor_sync(0xFFFFFFFFu, cb[nt][1], off);
                }
            if (lane < 4) {
                float* dA = g_agg + (size_t)rA * M_N + n0;
                float* dB = g_agg + (size_t)rB * M_N + n0;
                #pragma unroll
                for (int nt = 0; nt < 4; nt++) {
                    const int col = nbw + nt * 8 + 2 * c4;
                    atomicAdd(dA + col,     ca[nt][0]);
                    atomicAdd(dA + col + 1, ca[nt][1]);
                    atomicAdd(dB + col,     cb[nt][0]);
                    atomicAdd(dB + col + 1, cb[nt][1]);
                }
            }
        } else {
            // rare: >2 receivers in strip — per-row atomics
            #pragma unroll
            for (int mt = 0; mt < 4; mt++) {
                const int row0 = mb + mt * 16 + r4;
                const int row1 = row0 + 8;
                const float w0 = s_relt[row0];
                const float w1 = s_relt[row1];
                float* d0 = g_agg + (size_t)s_r[row0] * M_N + n0;
                float* d1 = g_agg + (size_t)s_r[row1] * M_N + n0;
                #pragma unroll
                for (int nt = 0; nt < 4; nt++) {
                    const int col = nbw + nt * 8 + 2 * c4;
                    const float bb0 = s_b2[col];
                    const float bb1 = s_b2[col + 1];
                    atomicAdd(d0 + col,     w0 * fmaxf(acc[mt][nt][0] + bb0, 0.0f));
                    atomicAdd(d0 + col + 1, w0 * fmaxf(acc[mt][nt][1] + bb1, 0.0f));
                    atomicAdd(d1 + col,     w1 * fmaxf(acc[mt][nt][2] + bb0, 0.0f));
                    atomicAdd(d1 + col + 1, w1 * fmaxf(acc[mt][nt][3] + bb1, 0.0f));
                }
            }
        }
    }
}

// ---------------------------------------------------------------------------
// Launch
// ---------------------------------------------------------------------------
extern "C" void kernel_launch(void* const* d_in, const int* in_sizes, int n_in,
                              void* d_out, int out_size)
{
    const float* inputs = (const float*)d_in[0];
    const float* rel    = (const float*)d_in[1];
    const float* W1     = (const float*)d_in[2];
    const float* b1     = (const float*)d_in[3];
    const float* W2     = (const float*)d_in[4];
    const float* b2     = (const float*)d_in[5];
    const float* Wo1    = (const float*)d_in[6];
    const float* bo1    = (const float*)d_in[7];
    const float* Wo2    = (const float*)d_in[8];
    const float* bo2    = (const float*)d_in[9];
    const float* Wo3    = (const float*)d_in[10];
    const float* bo3    = (const float*)d_in[11];
    const int* send_idx = (const int*)d_in[12];
    const int* rec_idx  = (const int*)d_in[13];
    float* out = (float*)d_out;

    float *pAgg, *pH1, *pH2;
    cudaGetSymbolAddress((void**)&pAgg, g_agg);
    cudaGetSymbolAddress((void**)&pH1, g_h1);
    cudaGetSymbolAddress((void**)&pH2, g_h2);

    cudaFuncSetAttribute(edge_mma_kernel,
                         cudaFuncAttributeMaxDynamicSharedMemorySize, EDGE_SMEM);

    // Prep: transpose (+zeroing) + projections + receiver sort
    transpose_w2_h<<<dim3(H_N / 32, M_N / 32, 2), dim3(32, 8)>>>(W2);
    layer1_gemm_h<<<dim3(H_N / 64, C_N / 32, 4), 256>>>(inputs, W1, b1);
    hist_kernel<<<128, 512>>>(rec_idx);
    scan_kernel<<<1, 512>>>();
    mkperm_kernel<<<256, 256>>>(rec_idx);

    // Main edge GEMM: persistent CTAs, B resident, KC=64, dynamic tiles
    edge_mma_kernel<<<dim3(152, 4), 512, EDGE_SMEM>>>(
        b2, rel, send_idx, rec_idx);

    // Output MLP (fp32, 32x64 tiles)
    gemm32<<<dim3(OH_N / 64, C_N / 32), 256>>>(pAgg, Wo1, bo1, pH1, M_N, OH_N, 1);
    gemm32<<<dim3(OH_N / 64, C_N / 32), 256>>>(pH1, Wo2, bo2, pH2, OH_N, OH_N, 1);
    gemm32<<<dim3(D_N / 64, C_N / 32), 256>>>(pH2, Wo3, bo3, out, OH_N, D_N, 0);
}